// round 1
// baseline (speedup 1.0000x reference)
#include <cuda_runtime.h>
#include <cuda_bf16.h>
#include <math.h>

#define Nn 100000
#define Ee 1600000
#define ET (Ee + Nn)
#define NG 10000

// ---------------- scratch (static device memory; no allocs) ----------------
__device__ int   g_cnt[Nn];
__device__ int   g_rowptr[Nn + 1];
__device__ int   g_cursor[Nn];
__device__ int   g_col[ET];
__device__ float g_w[ET];
__device__ float g_dinv[Nn];
__device__ float g_bufA[(size_t)Nn * 128];
__device__ float g_bufB[(size_t)Nn * 128];
__device__ float g_h[(size_t)Nn * 64];     // GAT transformed features
__device__ float g_gat[(size_t)Nn * 64];   // GAT output
__device__ float g_as[Nn];
__device__ float g_ad[Nn];
__device__ float g_m1[(size_t)NG * 512];
__device__ float g_m2[(size_t)NG * 256];

// ---------------- preprocessing ----------------
__global__ void init_cnt() {
    int i = blockIdx.x * blockDim.x + threadIdx.x;
    if (i < Nn) g_cnt[i] = 1;   // self loop
}

__global__ void count_deg(const int* __restrict__ dst) {
    int i = blockIdx.x * blockDim.x + threadIdx.x;
    if (i < Ee) atomicAdd(&g_cnt[dst[i]], 1);
}

__global__ void calc_dinv() {
    int i = blockIdx.x * blockDim.x + threadIdx.x;
    if (i < Nn) g_dinv[i] = rsqrtf((float)g_cnt[i]);
}

// single-block exclusive scan of g_cnt -> g_rowptr / g_cursor
__global__ void scan_kernel() {
    __shared__ int ssum[1024];
    int t = threadIdx.x;
    const int C = (Nn + 1023) / 1024;   // 98
    int beg = t * C;
    int end = beg + C; if (end > Nn) end = Nn;
    int s = 0;
    for (int i = beg; i < end; ++i) s += g_cnt[i];
    ssum[t] = s;
    __syncthreads();
    // Hillis-Steele inclusive scan
    for (int off = 1; off < 1024; off <<= 1) {
        int v = (t >= off) ? ssum[t - off] : 0;
        __syncthreads();
        ssum[t] += v;
        __syncthreads();
    }
    int run = (t == 0) ? 0 : ssum[t - 1];
    for (int i = beg; i < end; ++i) {
        g_rowptr[i] = run;
        g_cursor[i] = run;
        run += g_cnt[i];
    }
    if (t == 1023) g_rowptr[Nn] = ssum[1023];
}

__global__ void fill_csr(const int* __restrict__ src, const int* __restrict__ dst) {
    int i = blockIdx.x * blockDim.x + threadIdx.x;
    if (i >= ET) return;
    if (i < Ee) {
        int s = src[i], d = dst[i];
        int p = atomicAdd(&g_cursor[d], 1);
        g_col[p] = s;
        g_w[p] = g_dinv[s] * g_dinv[d];
    } else {
        int v = i - Ee;
        int p = atomicAdd(&g_cursor[v], 1);
        g_col[p] = v;
        float dv = g_dinv[v];
        g_w[p] = dv * dv;
    }
}

// ---------------- SpMM: out[dst,:] = sum_e w * in[src,:]  (128 features) ----
__global__ void __launch_bounds__(256) spmm128(const float* __restrict__ in,
                                               float* __restrict__ out) {
    int w = (blockIdx.x * blockDim.x + threadIdx.x) >> 5;
    if (w >= Nn) return;
    int lane = threadIdx.x & 31;
    int beg = g_rowptr[w], end = g_rowptr[w + 1];
    const float4* in4 = (const float4*)in;
    float4 acc = make_float4(0.f, 0.f, 0.f, 0.f);
    for (int e = beg; e < end; ++e) {
        int s = g_col[e];
        float ww = g_w[e];
        float4 v = __ldg(&in4[(size_t)s * 32 + lane]);
        acc.x = fmaf(ww, v.x, acc.x);
        acc.y = fmaf(ww, v.y, acc.y);
        acc.z = fmaf(ww, v.z, acc.z);
        acc.w = fmaf(ww, v.w, acc.w);
    }
    ((float4*)out)[(size_t)w * 32 + lane] = acc;
}

// ---------------- generic fp32 GEMM + bias + leaky-relu ----------------
// C[M,Nc] = act(A[M,K] @ B[K,Nc] + bias).  Requires K%16==0, Nc%64==0.
__global__ void __launch_bounds__(256) gemm_bias_act(
    const float* __restrict__ A, const float* __restrict__ B,
    const float* __restrict__ bias, float* __restrict__ C,
    int M, int Nc, int K, float slope, int act)
{
    const int BM = 64, BN = 64, BK = 16;
    __shared__ __align__(16) float As[BK][BM];
    __shared__ __align__(16) float Bs[BK][BN];
    int tid = threadIdx.x;
    int bm = blockIdx.y * BM;
    int bn = blockIdx.x * BN;
    int tr = (tid >> 4) * 4;
    int tc = (tid & 15) * 4;
    float acc[4][4];
#pragma unroll
    for (int i = 0; i < 4; i++)
#pragma unroll
        for (int j = 0; j < 4; j++) acc[i][j] = 0.f;

    int aRow = tid >> 2;
    int aCol = (tid & 3) * 4;
    int bRow = tid >> 4;
    int bCol = (tid & 15) * 4;
    bool aValid = (bm + aRow) < M;
    const float* Aptr = A + (size_t)(bm + aRow) * K + aCol;

    for (int k0 = 0; k0 < K; k0 += BK) {
        float4 a4 = make_float4(0.f, 0.f, 0.f, 0.f);
        if (aValid) a4 = *(const float4*)(Aptr + k0);
        float4 b4 = *(const float4*)(B + (size_t)(k0 + bRow) * Nc + bn + bCol);
        As[aCol + 0][aRow] = a4.x;
        As[aCol + 1][aRow] = a4.y;
        As[aCol + 2][aRow] = a4.z;
        As[aCol + 3][aRow] = a4.w;
        *(float4*)&Bs[bRow][bCol] = b4;
        __syncthreads();
#pragma unroll
        for (int k = 0; k < BK; k++) {
            float4 av = *(const float4*)&As[k][tr];
            float4 bv = *(const float4*)&Bs[k][tc];
            float ar[4] = {av.x, av.y, av.z, av.w};
            float br[4] = {bv.x, bv.y, bv.z, bv.w};
#pragma unroll
            for (int i = 0; i < 4; i++)
#pragma unroll
                for (int j = 0; j < 4; j++)
                    acc[i][j] = fmaf(ar[i], br[j], acc[i][j]);
        }
        __syncthreads();
    }

#pragma unroll
    for (int i = 0; i < 4; i++) {
        int row = bm + tr + i;
        if (row >= M) continue;
        float4 o = make_float4(acc[i][0], acc[i][1], acc[i][2], acc[i][3]);
        if (bias) {
            o.x += bias[bn + tc + 0];
            o.y += bias[bn + tc + 1];
            o.z += bias[bn + tc + 2];
            o.w += bias[bn + tc + 3];
        }
        if (act) {
            o.x = o.x >= 0.f ? o.x : slope * o.x;
            o.y = o.y >= 0.f ? o.y : slope * o.y;
            o.z = o.z >= 0.f ? o.z : slope * o.z;
            o.w = o.w >= 0.f ? o.w : slope * o.w;
        }
        *(float4*)(C + (size_t)row * Nc + bn + tc) = o;
    }
}

// ---------------- GAT ----------------
__global__ void __launch_bounds__(256) att_scores(const float* __restrict__ h,
                                                  const float* __restrict__ att_s,
                                                  const float* __restrict__ att_d) {
    int w = (blockIdx.x * blockDim.x + threadIdx.x) >> 5;
    if (w >= Nn) return;
    int lane = threadIdx.x & 31;
    float h0 = h[(size_t)w * 64 + lane];
    float h1 = h[(size_t)w * 64 + 32 + lane];
    float s = h0 * att_s[lane] + h1 * att_s[32 + lane];
    float d = h0 * att_d[lane] + h1 * att_d[32 + lane];
#pragma unroll
    for (int off = 16; off > 0; off >>= 1) {
        s += __shfl_down_sync(0xffffffffu, s, off);
        d += __shfl_down_sync(0xffffffffu, d, off);
    }
    if (lane == 0) { g_as[w] = s; g_ad[w] = d; }
}

__global__ void __launch_bounds__(256) gat_aggregate(const float* __restrict__ h,
                                                     const float* __restrict__ bg,
                                                     float* __restrict__ out) {
    int row = (blockIdx.x * blockDim.x + threadIdx.x) >> 5;
    if (row >= Nn) return;
    int lane = threadIdx.x & 31;
    int beg = g_rowptr[row], end = g_rowptr[row + 1];
    float ad = g_ad[row];

    // pass 1: segment max over lrelu(a_s[src]+a_d[dst], 0.2)
    float m = -1e30f;
    for (int e = beg + lane; e < end; e += 32) {
        float v = g_as[g_col[e]] + ad;
        v = v >= 0.f ? v : 0.2f * v;
        m = fmaxf(m, v);
    }
#pragma unroll
    for (int off = 16; off > 0; off >>= 1)
        m = fmaxf(m, __shfl_xor_sync(0xffffffffu, m, off));

    // pass 2: sum of exp, and weighted feature accumulation (lane -> 2 feats)
    const float2* h2 = (const float2*)h;
    float2 acc = make_float2(0.f, 0.f);
    float ssum = 0.f;
    for (int e = beg; e < end; ++e) {
        int s = g_col[e];
        float v = g_as[s] + ad;
        v = v >= 0.f ? v : 0.2f * v;
        float c = __expf(v - m);
        ssum += c;
        float2 hv = __ldg(&h2[(size_t)s * 32 + lane]);
        acc.x = fmaf(c, hv.x, acc.x);
        acc.y = fmaf(c, hv.y, acc.y);
    }
    float inv = 1.0f / ssum;
    float o0 = acc.x * inv + bg[2 * lane];
    float o1 = acc.y * inv + bg[2 * lane + 1];
    o0 = o0 >= 0.f ? o0 : 0.1f * o0;
    o1 = o1 >= 0.f ? o1 : 0.1f * o1;
    ((float2*)out)[(size_t)row * 32 + lane] = make_float2(o0, o1);
}

// ---------------- final 256 -> 8 layer ----------------
__global__ void __launch_bounds__(256) final_layer(const float* __restrict__ A,
                                                   const float* __restrict__ W,
                                                   const float* __restrict__ b,
                                                   float* __restrict__ out) {
    __shared__ float Ws[256 * 8];
    int t = threadIdx.x;
    for (int i = t; i < 256 * 8; i += 256) Ws[i] = W[i];
    __syncthreads();
    int g = blockIdx.x * 32 + (t >> 3);
    int c = t & 7;
    if (g >= NG) return;
    const float* a = A + (size_t)g * 256;
    float acc = 0.f;
#pragma unroll 4
    for (int k = 0; k < 256; k++) acc = fmaf(a[k], Ws[k * 8 + c], acc);
    out[(size_t)g * 8 + c] = acc + b[c];
}

// ---------------- host launcher ----------------
extern "C" void kernel_launch(void* const* d_in, const int* in_sizes, int n_in,
                              void* d_out, int out_size) {
    const float* x     = (const float*)d_in[0];
    const int*   ei    = (const int*)d_in[1];
    const float* W1    = (const float*)d_in[2];
    const float* b1    = (const float*)d_in[3];
    const float* W2    = (const float*)d_in[4];
    const float* b2    = (const float*)d_in[5];
    const float* Wg    = (const float*)d_in[6];
    const float* att_s = (const float*)d_in[7];
    const float* att_d = (const float*)d_in[8];
    const float* bg    = (const float*)d_in[9];
    const float* Wl1   = (const float*)d_in[10];
    const float* bl1   = (const float*)d_in[11];
    const float* Wl2   = (const float*)d_in[12];
    const float* bl2   = (const float*)d_in[13];
    const float* Wl3   = (const float*)d_in[14];
    const float* bl3   = (const float*)d_in[15];
    float* out = (float*)d_out;

    const int* src = ei;
    const int* dst = ei + Ee;

    float *A, *B, *H, *G, *M1, *M2;
    cudaGetSymbolAddress((void**)&A,  g_bufA);
    cudaGetSymbolAddress((void**)&B,  g_bufB);
    cudaGetSymbolAddress((void**)&H,  g_h);
    cudaGetSymbolAddress((void**)&G,  g_gat);
    cudaGetSymbolAddress((void**)&M1, g_m1);
    cudaGetSymbolAddress((void**)&M2, g_m2);

    // ---- preprocessing: degrees, dinv, CSR grouped by dst ----
    init_cnt<<<(Nn + 255) / 256, 256>>>();
    count_deg<<<(Ee + 255) / 256, 256>>>(dst);
    calc_dinv<<<(Nn + 255) / 256, 256>>>();
    scan_kernel<<<1, 1024>>>();
    fill_csr<<<(ET + 255) / 256, 256>>>(src, dst);

    const int WARP_GRID = (Nn * 32 + 255) / 256;   // 12500

    // ---- conv1: 2 hops + linear + lrelu(0.1) ----
    spmm128<<<WARP_GRID, 256>>>(x, A);
    spmm128<<<WARP_GRID, 256>>>(A, B);
    {
        dim3 g(128 / 64, (Nn + 63) / 64);
        gemm_bias_act<<<g, 256>>>(B, W1, b1, A, Nn, 128, 128, 0.1f, 1);
    }

    // ---- conv2: 2 hops + linear + lrelu(0.1) ----
    spmm128<<<WARP_GRID, 256>>>(A, B);
    spmm128<<<WARP_GRID, 256>>>(B, A);
    {
        dim3 g(128 / 64, (Nn + 63) / 64);
        gemm_bias_act<<<g, 256>>>(A, W2, b2, B, Nn, 128, 128, 0.1f, 1);
    }

    // ---- GAT ----
    {
        dim3 g(64 / 64, (Nn + 63) / 64);
        gemm_bias_act<<<g, 256>>>(B, Wg, (const float*)nullptr, H, Nn, 64, 128, 0.f, 0);
    }
    att_scores<<<WARP_GRID, 256>>>(H, att_s, att_d);
    gat_aggregate<<<WARP_GRID, 256>>>(H, bg, G);

    // ---- MLP head (G viewed as [10000, 640]) ----
    {
        dim3 g(512 / 64, (NG + 63) / 64);
        gemm_bias_act<<<g, 256>>>(G, Wl1, bl1, M1, NG, 512, 640, 0.1f, 1);
    }
    {
        dim3 g(256 / 64, (NG + 63) / 64);
        gemm_bias_act<<<g, 256>>>(M1, Wl2, bl2, M2, NG, 256, 512, 0.1f, 1);
    }
    final_layer<<<(NG + 31) / 32, 256>>>(M2, Wl3, bl3, out);
}

// round 2
// speedup vs baseline: 1.1316x; 1.1316x over previous
#include <cuda_runtime.h>
#include <cuda_bf16.h>
#include <math.h>

#define Nn 100000
#define Ee 1600000
#define ET (Ee + Nn)
#define NG 10000
#define NBLK 98   // ceil(Nn/1024)

// ---------------- scratch (static device memory; no allocs) ----------------
__device__ int   g_cnt[Nn];
__device__ int   g_rowptr[Nn + 1];
__device__ int   g_cursor[Nn];
__device__ int   g_col[ET];
__device__ float g_w[ET];
__device__ float g_dinv[Nn];
__device__ int   g_bsum[128];
__device__ int   g_boff[128];
__device__ float g_bufA[(size_t)Nn * 128];
__device__ float g_bufB[(size_t)Nn * 128];
__device__ float g_h[(size_t)Nn * 64];     // GAT transformed features
__device__ float g_gat[(size_t)Nn * 64];   // GAT output
__device__ float g_as[Nn];
__device__ float g_ad[Nn];
__device__ float g_m1[(size_t)NG * 512];
__device__ float g_m2[(size_t)NG * 256];

// ---------------- preprocessing ----------------
__global__ void init_cnt() {
    int i = blockIdx.x * blockDim.x + threadIdx.x;
    if (i < Nn) g_cnt[i] = 1;   // self loop
}

__global__ void count_deg(const int* __restrict__ dst) {
    int i = blockIdx.x * blockDim.x + threadIdx.x;
    if (i < Ee) atomicAdd(&g_cnt[dst[i]], 1);
}

__global__ void calc_dinv() {
    int i = blockIdx.x * blockDim.x + threadIdx.x;
    if (i < Nn) g_dinv[i] = rsqrtf((float)g_cnt[i]);
}

// ---- 3-phase parallel exclusive scan of g_cnt -> g_rowptr / g_cursor ----
__global__ void __launch_bounds__(256) scan_p1() {
    __shared__ int ss[256];
    int b = blockIdx.x, t = threadIdx.x;
    int base = b * 1024 + t * 4;
    int4 v = make_int4(0, 0, 0, 0);
    if (base < Nn) v = *(const int4*)&g_cnt[base];
    ss[t] = v.x + v.y + v.z + v.w;
    __syncthreads();
    for (int off = 128; off > 0; off >>= 1) {
        if (t < off) ss[t] += ss[t + off];
        __syncthreads();
    }
    if (t == 0) g_bsum[b] = ss[0];
}

__global__ void scan_p2() {
    __shared__ int ss[128];
    int t = threadIdx.x;
    ss[t] = (t < NBLK) ? g_bsum[t] : 0;
    __syncthreads();
    for (int off = 1; off < 128; off <<= 1) {
        int u = (t >= off) ? ss[t - off] : 0;
        __syncthreads();
        ss[t] += u;
        __syncthreads();
    }
    g_boff[t] = (t == 0) ? 0 : ss[t - 1];
    if (t == 127) g_rowptr[Nn] = ss[127];
}

__global__ void __launch_bounds__(256) scan_p3() {
    __shared__ int ss[256];
    int b = blockIdx.x, t = threadIdx.x;
    int base = b * 1024 + t * 4;
    int4 v = make_int4(0, 0, 0, 0);
    if (base < Nn) v = *(const int4*)&g_cnt[base];
    int s0 = v.x, s1 = s0 + v.y, s2 = s1 + v.z, s3 = s2 + v.w;
    ss[t] = s3;
    __syncthreads();
    for (int off = 1; off < 256; off <<= 1) {
        int u = (t >= off) ? ss[t - off] : 0;
        __syncthreads();
        ss[t] += u;
        __syncthreads();
    }
    int ex = ((t == 0) ? 0 : ss[t - 1]) + g_boff[b];
    if (base < Nn) {
        int4 o = make_int4(ex, ex + s0, ex + s1, ex + s2);
        *(int4*)&g_rowptr[base] = o;
        *(int4*)&g_cursor[base] = o;
    }
}

__global__ void fill_csr(const int* __restrict__ src, const int* __restrict__ dst) {
    int i = blockIdx.x * blockDim.x + threadIdx.x;
    if (i >= ET) return;
    if (i < Ee) {
        int s = src[i], d = dst[i];
        int p = atomicAdd(&g_cursor[d], 1);
        g_col[p] = s;
        g_w[p] = g_dinv[s] * g_dinv[d];
    } else {
        int v = i - Ee;
        int p = atomicAdd(&g_cursor[v], 1);
        g_col[p] = v;
        float dv = g_dinv[v];
        g_w[p] = dv * dv;
    }
}

// ---------------- SpMM: out[dst,:] = sum_e w * in[src,:]  (128 features) ----
__global__ void __launch_bounds__(256) spmm128(const float* __restrict__ in,
                                               float* __restrict__ out) {
    int w = (blockIdx.x * blockDim.x + threadIdx.x) >> 5;
    if (w >= Nn) return;
    int lane = threadIdx.x & 31;
    int beg = g_rowptr[w], end = g_rowptr[w + 1];
    const float4* in4 = (const float4*)in;
    float4 acc = make_float4(0.f, 0.f, 0.f, 0.f);
    for (int e = beg; e < end; ++e) {
        int s = g_col[e];
        float ww = g_w[e];
        float4 v = __ldg(&in4[(size_t)s * 32 + lane]);
        acc.x = fmaf(ww, v.x, acc.x);
        acc.y = fmaf(ww, v.y, acc.y);
        acc.z = fmaf(ww, v.z, acc.z);
        acc.w = fmaf(ww, v.w, acc.w);
    }
    ((float4*)out)[(size_t)w * 32 + lane] = acc;
}

// ---------------- templated fp32 GEMM + bias + leaky-relu ----------------
// C[M,Nc] = act(A[M,K] @ B[K,Nc] + bias).  K%16==0, Nc%BN==0.
// BM=128, 256 threads, micro-tile 8 x TN (TN = BN/16).
template<int BN, int TN>
__global__ void __launch_bounds__(256) gemm_t(
    const float* __restrict__ A, const float* __restrict__ B,
    const float* __restrict__ bias, float* __restrict__ C,
    int M, int Nc, int K, float slope, int act)
{
    const int BM = 128, BK = 16, TM = 8;
    __shared__ __align__(16) float As[BK][BM];
    __shared__ __align__(16) float Bs[BK][BN];
    int tid = threadIdx.x;
    int bm = blockIdx.y * BM;
    int bn = blockIdx.x * BN;
    int tr = (tid >> 4) * TM;
    int tc = (tid & 15) * TN;
    float acc[TM][TN];
#pragma unroll
    for (int i = 0; i < TM; i++)
#pragma unroll
        for (int j = 0; j < TN; j++) acc[i][j] = 0.f;

    int aRow = tid >> 1;
    int aCol = (tid & 1) * 8;
    bool aValid = (bm + aRow) < M;
    const float* Aptr = A + (size_t)(bm + aRow) * K + aCol;
    int bRow = tid >> 4;
    int bCol = (tid & 15) * (BN / 16);

    for (int k0 = 0; k0 < K; k0 += BK) {
        float4 a0 = make_float4(0.f, 0.f, 0.f, 0.f), a1 = a0;
        if (aValid) {
            a0 = *(const float4*)(Aptr + k0);
            a1 = *(const float4*)(Aptr + k0 + 4);
        }
        As[aCol + 0][aRow] = a0.x; As[aCol + 1][aRow] = a0.y;
        As[aCol + 2][aRow] = a0.z; As[aCol + 3][aRow] = a0.w;
        As[aCol + 4][aRow] = a1.x; As[aCol + 5][aRow] = a1.y;
        As[aCol + 6][aRow] = a1.z; As[aCol + 7][aRow] = a1.w;
        const float* Bp = B + (size_t)(k0 + bRow) * Nc + bn + bCol;
        *(float4*)&Bs[bRow][bCol] = *(const float4*)Bp;
        if (BN == 128)
            *(float4*)&Bs[bRow][bCol + 4] = *(const float4*)(Bp + 4);
        __syncthreads();
#pragma unroll
        for (int k = 0; k < BK; k++) {
            float ar[TM], br[TN];
            float4 av0 = *(const float4*)&As[k][tr];
            float4 av1 = *(const float4*)&As[k][tr + 4];
            ar[0] = av0.x; ar[1] = av0.y; ar[2] = av0.z; ar[3] = av0.w;
            ar[4] = av1.x; ar[5] = av1.y; ar[6] = av1.z; ar[7] = av1.w;
            float4 bv0 = *(const float4*)&Bs[k][tc];
            br[0] = bv0.x; br[1] = bv0.y; br[2] = bv0.z; br[3] = bv0.w;
            if (TN == 8) {
                float4 bv1 = *(const float4*)&Bs[k][tc + 4];
                br[4] = bv1.x; br[5] = bv1.y; br[6] = bv1.z; br[7] = bv1.w;
            }
#pragma unroll
            for (int i = 0; i < TM; i++)
#pragma unroll
                for (int j = 0; j < TN; j++)
                    acc[i][j] = fmaf(ar[i], br[j], acc[i][j]);
        }
        __syncthreads();
    }

#pragma unroll
    for (int i = 0; i < TM; i++) {
        int row = bm + tr + i;
        if (row >= M) continue;
#pragma unroll
        for (int j0 = 0; j0 < TN; j0 += 4) {
            float4 o = make_float4(acc[i][j0], acc[i][j0 + 1],
                                   acc[i][j0 + 2], acc[i][j0 + 3]);
            if (bias) {
                o.x += bias[bn + tc + j0 + 0];
                o.y += bias[bn + tc + j0 + 1];
                o.z += bias[bn + tc + j0 + 2];
                o.w += bias[bn + tc + j0 + 3];
            }
            if (act) {
                o.x = o.x >= 0.f ? o.x : slope * o.x;
                o.y = o.y >= 0.f ? o.y : slope * o.y;
                o.z = o.z >= 0.f ? o.z : slope * o.z;
                o.w = o.w >= 0.f ? o.w : slope * o.w;
            }
            *(float4*)(C + (size_t)row * Nc + bn + tc + j0) = o;
        }
    }
}

// ---------------- GAT ----------------
__global__ void __launch_bounds__(256) att_scores(const float* __restrict__ h,
                                                  const float* __restrict__ att_s,
                                                  const float* __restrict__ att_d) {
    int w = (blockIdx.x * blockDim.x + threadIdx.x) >> 5;
    if (w >= Nn) return;
    int lane = threadIdx.x & 31;
    float h0 = h[(size_t)w * 64 + lane];
    float h1 = h[(size_t)w * 64 + 32 + lane];
    float s = h0 * att_s[lane] + h1 * att_s[32 + lane];
    float d = h0 * att_d[lane] + h1 * att_d[32 + lane];
#pragma unroll
    for (int off = 16; off > 0; off >>= 1) {
        s += __shfl_down_sync(0xffffffffu, s, off);
        d += __shfl_down_sync(0xffffffffu, d, off);
    }
    if (lane == 0) { g_as[w] = s; g_ad[w] = d; }
}

__global__ void __launch_bounds__(256) gat_aggregate(const float* __restrict__ h,
                                                     const float* __restrict__ bg,
                                                     float* __restrict__ out) {
    int row = (blockIdx.x * blockDim.x + threadIdx.x) >> 5;
    if (row >= Nn) return;
    int lane = threadIdx.x & 31;
    int beg = g_rowptr[row], end = g_rowptr[row + 1];
    float ad = g_ad[row];

    float m = -1e30f;
    for (int e = beg + lane; e < end; e += 32) {
        float v = g_as[g_col[e]] + ad;
        v = v >= 0.f ? v : 0.2f * v;
        m = fmaxf(m, v);
    }
#pragma unroll
    for (int off = 16; off > 0; off >>= 1)
        m = fmaxf(m, __shfl_xor_sync(0xffffffffu, m, off));

    const float2* h2 = (const float2*)h;
    float2 acc = make_float2(0.f, 0.f);
    float ssum = 0.f;
    for (int e = beg; e < end; ++e) {
        int s = g_col[e];
        float v = g_as[s] + ad;
        v = v >= 0.f ? v : 0.2f * v;
        float c = __expf(v - m);
        ssum += c;
        float2 hv = __ldg(&h2[(size_t)s * 32 + lane]);
        acc.x = fmaf(c, hv.x, acc.x);
        acc.y = fmaf(c, hv.y, acc.y);
    }
    float inv = 1.0f / ssum;
    float o0 = acc.x * inv + bg[2 * lane];
    float o1 = acc.y * inv + bg[2 * lane + 1];
    o0 = o0 >= 0.f ? o0 : 0.1f * o0;
    o1 = o1 >= 0.f ? o1 : 0.1f * o1;
    ((float2*)out)[(size_t)row * 32 + lane] = make_float2(o0, o1);
}

// ---------------- final 256 -> 8 layer ----------------
__global__ void __launch_bounds__(256) final_layer(const float* __restrict__ A,
                                                   const float* __restrict__ W,
                                                   const float* __restrict__ b,
                                                   float* __restrict__ out) {
    __shared__ float Ws[256 * 8];
    int t = threadIdx.x;
    for (int i = t; i < 256 * 8; i += 256) Ws[i] = W[i];
    __syncthreads();
    int g = blockIdx.x * 32 + (t >> 3);
    int c = t & 7;
    if (g >= NG) return;
    const float* a = A + (size_t)g * 256;
    float acc = 0.f;
#pragma unroll 4
    for (int k = 0; k < 256; k++) acc = fmaf(a[k], Ws[k * 8 + c], acc);
    out[(size_t)g * 8 + c] = acc + b[c];
}

// ---------------- host launcher ----------------
extern "C" void kernel_launch(void* const* d_in, const int* in_sizes, int n_in,
                              void* d_out, int out_size) {
    const float* x     = (const float*)d_in[0];
    const int*   ei    = (const int*)d_in[1];
    const float* W1    = (const float*)d_in[2];
    const float* b1    = (const float*)d_in[3];
    const float* W2    = (const float*)d_in[4];
    const float* b2    = (const float*)d_in[5];
    const float* Wg    = (const float*)d_in[6];
    const float* att_s = (const float*)d_in[7];
    const float* att_d = (const float*)d_in[8];
    const float* bg    = (const float*)d_in[9];
    const float* Wl1   = (const float*)d_in[10];
    const float* bl1   = (const float*)d_in[11];
    const float* Wl2   = (const float*)d_in[12];
    const float* bl2   = (const float*)d_in[13];
    const float* Wl3   = (const float*)d_in[14];
    const float* bl3   = (const float*)d_in[15];
    float* out = (float*)d_out;

    const int* src = ei;
    const int* dst = ei + Ee;

    float *A, *B, *H, *G, *M1, *M2;
    cudaGetSymbolAddress((void**)&A,  g_bufA);
    cudaGetSymbolAddress((void**)&B,  g_bufB);
    cudaGetSymbolAddress((void**)&H,  g_h);
    cudaGetSymbolAddress((void**)&G,  g_gat);
    cudaGetSymbolAddress((void**)&M1, g_m1);
    cudaGetSymbolAddress((void**)&M2, g_m2);

    // ---- preprocessing: degrees, dinv, CSR grouped by dst ----
    init_cnt<<<(Nn + 255) / 256, 256>>>();
    count_deg<<<(Ee + 255) / 256, 256>>>(dst);
    calc_dinv<<<(Nn + 255) / 256, 256>>>();
    scan_p1<<<NBLK, 256>>>();
    scan_p2<<<1, 128>>>();
    scan_p3<<<NBLK, 256>>>();
    fill_csr<<<(ET + 255) / 256, 256>>>(src, dst);

    const int WARP_GRID = (Nn * 32 + 255) / 256;   // 12500

    // ---- conv1: 2 hops + linear + lrelu(0.1) ----
    spmm128<<<WARP_GRID, 256>>>(x, A);
    spmm128<<<WARP_GRID, 256>>>(A, B);
    {
        dim3 g(1, (Nn + 127) / 128);
        gemm_t<128, 8><<<g, 256>>>(B, W1, b1, A, Nn, 128, 128, 0.1f, 1);
    }

    // ---- conv2: 2 hops + linear + lrelu(0.1) ----
    spmm128<<<WARP_GRID, 256>>>(A, B);
    spmm128<<<WARP_GRID, 256>>>(B, A);
    {
        dim3 g(1, (Nn + 127) / 128);
        gemm_t<128, 8><<<g, 256>>>(A, W2, b2, B, Nn, 128, 128, 0.1f, 1);
    }

    // ---- GAT ----
    {
        dim3 g(1, (Nn + 127) / 128);
        gemm_t<64, 4><<<g, 256>>>(B, Wg, (const float*)nullptr, H, Nn, 64, 128, 0.f, 0);
    }
    att_scores<<<WARP_GRID, 256>>>(H, att_s, att_d);
    gat_aggregate<<<WARP_GRID, 256>>>(H, bg, G);

    // ---- MLP head (G viewed as [10000, 640]) ----
    {
        dim3 g(512 / 128, (NG + 127) / 128);
        gemm_t<128, 8><<<g, 256>>>(G, Wl1, bl1, M1, NG, 512, 640, 0.1f, 1);
    }
    {
        dim3 g(256 / 128, (NG + 127) / 128);
        gemm_t<128, 8><<<g, 256>>>(M1, Wl2, bl2, M2, NG, 256, 512, 0.1f, 1);
    }
    final_layer<<<(NG + 31) / 32, 256>>>(M2, Wl3, bl3, out);
}

// round 3
// speedup vs baseline: 1.1416x; 1.0089x over previous
#include <cuda_runtime.h>
#include <cuda_bf16.h>
#include <math.h>

#define Nn 100000
#define Ee 1600000
#define ET (Ee + Nn)
#define NG 10000
#define NBLK 98   // ceil(Nn/1024)

// ---------------- scratch (static device memory; no allocs) ----------------
__device__ int   g_cnt[Nn];
__device__ int   g_rowptr[Nn + 1];
__device__ int   g_cursor[Nn];
__device__ int   g_col[ET];
__device__ float g_w[ET];
__device__ float g_dinv[Nn];
__device__ int   g_bsum[128];
__device__ int   g_boff[128];
__device__ float g_bufA[(size_t)Nn * 128];
__device__ float g_bufB[(size_t)Nn * 128];
__device__ float g_h[(size_t)Nn * 64];     // GAT transformed features
__device__ float g_gat[(size_t)Nn * 64];   // GAT output
__device__ float g_as[Nn];
__device__ float g_ad[Nn];
__device__ float g_m1[(size_t)NG * 512];
__device__ float g_m2[(size_t)NG * 256];

// ---------------- preprocessing ----------------
__global__ void init_cnt() {
    int i = blockIdx.x * blockDim.x + threadIdx.x;
    if (i < Nn) g_cnt[i] = 1;   // self loop
}

__global__ void count_deg(const int* __restrict__ dst) {
    int i = blockIdx.x * blockDim.x + threadIdx.x;
    if (i < Ee) atomicAdd(&g_cnt[dst[i]], 1);
}

__global__ void calc_dinv() {
    int i = blockIdx.x * blockDim.x + threadIdx.x;
    if (i < Nn) g_dinv[i] = rsqrtf((float)g_cnt[i]);
}

// ---- 3-phase parallel exclusive scan of g_cnt -> g_rowptr / g_cursor ----
__global__ void __launch_bounds__(256) scan_p1() {
    __shared__ int ss[256];
    int b = blockIdx.x, t = threadIdx.x;
    int base = b * 1024 + t * 4;
    int4 v = make_int4(0, 0, 0, 0);
    if (base < Nn) v = *(const int4*)&g_cnt[base];
    ss[t] = v.x + v.y + v.z + v.w;
    __syncthreads();
    for (int off = 128; off > 0; off >>= 1) {
        if (t < off) ss[t] += ss[t + off];
        __syncthreads();
    }
    if (t == 0) g_bsum[b] = ss[0];
}

__global__ void scan_p2() {
    __shared__ int ss[128];
    int t = threadIdx.x;
    ss[t] = (t < NBLK) ? g_bsum[t] : 0;
    __syncthreads();
    for (int off = 1; off < 128; off <<= 1) {
        int u = (t >= off) ? ss[t - off] : 0;
        __syncthreads();
        ss[t] += u;
        __syncthreads();
    }
    g_boff[t] = (t == 0) ? 0 : ss[t - 1];
    if (t == 127) g_rowptr[Nn] = ss[127];
}

__global__ void __launch_bounds__(256) scan_p3() {
    __shared__ int ss[256];
    int b = blockIdx.x, t = threadIdx.x;
    int base = b * 1024 + t * 4;
    int4 v = make_int4(0, 0, 0, 0);
    if (base < Nn) v = *(const int4*)&g_cnt[base];
    int s0 = v.x, s1 = s0 + v.y, s2 = s1 + v.z, s3 = s2 + v.w;
    ss[t] = s3;
    __syncthreads();
    for (int off = 1; off < 256; off <<= 1) {
        int u = (t >= off) ? ss[t - off] : 0;
        __syncthreads();
        ss[t] += u;
        __syncthreads();
    }
    int ex = ((t == 0) ? 0 : ss[t - 1]) + g_boff[b];
    if (base < Nn) {
        int4 o = make_int4(ex, ex + s0, ex + s1, ex + s2);
        *(int4*)&g_rowptr[base] = o;
        *(int4*)&g_cursor[base] = o;
    }
}

__global__ void fill_csr(const int* __restrict__ src, const int* __restrict__ dst) {
    int i = blockIdx.x * blockDim.x + threadIdx.x;
    if (i >= ET) return;
    if (i < Ee) {
        int s = src[i], d = dst[i];
        int p = atomicAdd(&g_cursor[d], 1);
        g_col[p] = s;
        g_w[p] = g_dinv[s] * g_dinv[d];
    } else {
        int v = i - Ee;
        int p = atomicAdd(&g_cursor[v], 1);
        g_col[p] = v;
        float dv = g_dinv[v];
        g_w[p] = dv * dv;
    }
}

// ---------------- SpMM: out[dst,:] = sum_e w * in[src,:]  (128 features) ----
__global__ void __launch_bounds__(256) spmm128(const float* __restrict__ in,
                                               float* __restrict__ out) {
    int w = (blockIdx.x * blockDim.x + threadIdx.x) >> 5;
    if (w >= Nn) return;
    int lane = threadIdx.x & 31;
    int beg = g_rowptr[w], end = g_rowptr[w + 1];
    const float4* in4 = (const float4*)in;
    float4 acc = make_float4(0.f, 0.f, 0.f, 0.f);
    for (int e = beg; e < end; ++e) {
        int s = g_col[e];
        float ww = g_w[e];
        float4 v = __ldg(&in4[(size_t)s * 32 + lane]);
        acc.x = fmaf(ww, v.x, acc.x);
        acc.y = fmaf(ww, v.y, acc.y);
        acc.z = fmaf(ww, v.z, acc.z);
        acc.w = fmaf(ww, v.w, acc.w);
    }
    ((float4*)out)[(size_t)w * 32 + lane] = acc;
}

// ---------------- FFMA2 (fma.rn.f32x2) fp32 GEMM + bias + leaky-relu -------
// C[M,Nc] = act(A[M,K] @ B[K,Nc] + bias).  K%16==0, Nc%BN==0.
// BM=128, 256 threads, micro-tile 8 x TN. Accumulators are f32x2 pairs.
template<int BN, int TN>
__global__ void __launch_bounds__(256) gemm_t(
    const float* __restrict__ A, const float* __restrict__ B,
    const float* __restrict__ bias, float* __restrict__ C,
    int M, int Nc, int K, float slope, int act)
{
    const int BM = 128, BK = 16, TM = 8;
    __shared__ __align__(16) float As[BK][BM];
    __shared__ __align__(16) float Bs[BK][BN];
    int tid = threadIdx.x;
    int bm = blockIdx.y * BM;
    int bn = blockIdx.x * BN;
    int tr = (tid >> 4) * TM;
    int tc = (tid & 15) * TN;

    unsigned long long acc64[TM][TN / 2];
#pragma unroll
    for (int i = 0; i < TM; i++)
#pragma unroll
        for (int j = 0; j < TN / 2; j++) acc64[i][j] = 0ull;

    int aRow = tid >> 1;
    int aCol = (tid & 1) * 8;
    bool aValid = (bm + aRow) < M;
    const float* Aptr = A + (size_t)(bm + aRow) * K + aCol;
    int bRow = tid >> 4;
    int bCol = (tid & 15) * (BN / 16);

    for (int k0 = 0; k0 < K; k0 += BK) {
        float4 a0 = make_float4(0.f, 0.f, 0.f, 0.f), a1 = a0;
        if (aValid) {
            a0 = *(const float4*)(Aptr + k0);
            a1 = *(const float4*)(Aptr + k0 + 4);
        }
        As[aCol + 0][aRow] = a0.x; As[aCol + 1][aRow] = a0.y;
        As[aCol + 2][aRow] = a0.z; As[aCol + 3][aRow] = a0.w;
        As[aCol + 4][aRow] = a1.x; As[aCol + 5][aRow] = a1.y;
        As[aCol + 6][aRow] = a1.z; As[aCol + 7][aRow] = a1.w;
        const float* Bp = B + (size_t)(k0 + bRow) * Nc + bn + bCol;
        *(float4*)&Bs[bRow][bCol] = *(const float4*)Bp;
        if (BN == 128)
            *(float4*)&Bs[bRow][bCol + 4] = *(const float4*)(Bp + 4);
        __syncthreads();
#pragma unroll
        for (int k = 0; k < BK; k++) {
            float ar[TM];
            float4 av0 = *(const float4*)&As[k][tr];
            float4 av1 = *(const float4*)&As[k][tr + 4];
            ar[0] = av0.x; ar[1] = av0.y; ar[2] = av0.z; ar[3] = av0.w;
            ar[4] = av1.x; ar[5] = av1.y; ar[6] = av1.z; ar[7] = av1.w;

            unsigned long long bp[TN / 2];
            float4 bv0 = *(const float4*)&Bs[k][tc];
            asm("mov.b64 %0, {%1,%2};" : "=l"(bp[0]) : "f"(bv0.x), "f"(bv0.y));
            asm("mov.b64 %0, {%1,%2};" : "=l"(bp[1]) : "f"(bv0.z), "f"(bv0.w));
            if (TN == 8) {
                float4 bv1 = *(const float4*)&Bs[k][tc + 4];
                asm("mov.b64 %0, {%1,%2};" : "=l"(bp[2]) : "f"(bv1.x), "f"(bv1.y));
                asm("mov.b64 %0, {%1,%2};" : "=l"(bp[3]) : "f"(bv1.z), "f"(bv1.w));
            }
#pragma unroll
            for (int i = 0; i < TM; i++) {
                unsigned long long ad;
                asm("mov.b64 %0, {%1,%1};" : "=l"(ad) : "f"(ar[i]));
#pragma unroll
                for (int j = 0; j < TN / 2; j++)
                    asm("fma.rn.f32x2 %0, %1, %2, %0;"
                        : "+l"(acc64[i][j]) : "l"(ad), "l"(bp[j]));
            }
        }
        __syncthreads();
    }

#pragma unroll
    for (int i = 0; i < TM; i++) {
        int row = bm + tr + i;
        if (row >= M) continue;
        float accf[TN];
#pragma unroll
        for (int j = 0; j < TN / 2; j++)
            asm("mov.b64 {%0,%1}, %2;"
                : "=f"(accf[2 * j]), "=f"(accf[2 * j + 1]) : "l"(acc64[i][j]));
#pragma unroll
        for (int j0 = 0; j0 < TN; j0 += 4) {
            float4 o = make_float4(accf[j0], accf[j0 + 1], accf[j0 + 2], accf[j0 + 3]);
            if (bias) {
                o.x += bias[bn + tc + j0 + 0];
                o.y += bias[bn + tc + j0 + 1];
                o.z += bias[bn + tc + j0 + 2];
                o.w += bias[bn + tc + j0 + 3];
            }
            if (act) {
                o.x = o.x >= 0.f ? o.x : slope * o.x;
                o.y = o.y >= 0.f ? o.y : slope * o.y;
                o.z = o.z >= 0.f ? o.z : slope * o.z;
                o.w = o.w >= 0.f ? o.w : slope * o.w;
            }
            *(float4*)(C + (size_t)row * Nc + bn + tc + j0) = o;
        }
    }
}

// ---------------- GAT ----------------
__global__ void __launch_bounds__(256) att_scores(const float* __restrict__ h,
                                                  const float* __restrict__ att_s,
                                                  const float* __restrict__ att_d) {
    int w = (blockIdx.x * blockDim.x + threadIdx.x) >> 5;
    if (w >= Nn) return;
    int lane = threadIdx.x & 31;
    float h0 = h[(size_t)w * 64 + lane];
    float h1 = h[(size_t)w * 64 + 32 + lane];
    float s = h0 * att_s[lane] + h1 * att_s[32 + lane];
    float d = h0 * att_d[lane] + h1 * att_d[32 + lane];
#pragma unroll
    for (int off = 16; off > 0; off >>= 1) {
        s += __shfl_down_sync(0xffffffffu, s, off);
        d += __shfl_down_sync(0xffffffffu, d, off);
    }
    if (lane == 0) { g_as[w] = s; g_ad[w] = d; }
}

__global__ void __launch_bounds__(256) gat_aggregate(const float* __restrict__ h,
                                                     const float* __restrict__ bg,
                                                     float* __restrict__ out) {
    int row = (blockIdx.x * blockDim.x + threadIdx.x) >> 5;
    if (row >= Nn) return;
    int lane = threadIdx.x & 31;
    int beg = g_rowptr[row], end = g_rowptr[row + 1];
    float ad = g_ad[row];

    float m = -1e30f;
    for (int e = beg + lane; e < end; e += 32) {
        float v = g_as[g_col[e]] + ad;
        v = v >= 0.f ? v : 0.2f * v;
        m = fmaxf(m, v);
    }
#pragma unroll
    for (int off = 16; off > 0; off >>= 1)
        m = fmaxf(m, __shfl_xor_sync(0xffffffffu, m, off));

    const float2* h2 = (const float2*)h;
    float2 acc = make_float2(0.f, 0.f);
    float ssum = 0.f;
    for (int e = beg; e < end; ++e) {
        int s = g_col[e];
        float v = g_as[s] + ad;
        v = v >= 0.f ? v : 0.2f * v;
        float c = __expf(v - m);
        ssum += c;
        float2 hv = __ldg(&h2[(size_t)s * 32 + lane]);
        acc.x = fmaf(c, hv.x, acc.x);
        acc.y = fmaf(c, hv.y, acc.y);
    }
    float inv = 1.0f / ssum;
    float o0 = acc.x * inv + bg[2 * lane];
    float o1 = acc.y * inv + bg[2 * lane + 1];
    o0 = o0 >= 0.f ? o0 : 0.1f * o0;
    o1 = o1 >= 0.f ? o1 : 0.1f * o1;
    ((float2*)out)[(size_t)row * 32 + lane] = make_float2(o0, o1);
}

// ---------------- final 256 -> 8 layer ----------------
__global__ void __launch_bounds__(256) final_layer(const float* __restrict__ A,
                                                   const float* __restrict__ W,
                                                   const float* __restrict__ b,
                                                   float* __restrict__ out) {
    __shared__ float Ws[256 * 8];
    int t = threadIdx.x;
    for (int i = t; i < 256 * 8; i += 256) Ws[i] = W[i];
    __syncthreads();
    int g = blockIdx.x * 32 + (t >> 3);
    int c = t & 7;
    if (g >= NG) return;
    const float* a = A + (size_t)g * 256;
    float acc = 0.f;
#pragma unroll 4
    for (int k = 0; k < 256; k++) acc = fmaf(a[k], Ws[k * 8 + c], acc);
    out[(size_t)g * 8 + c] = acc + b[c];
}

// ---------------- host launcher ----------------
extern "C" void kernel_launch(void* const* d_in, const int* in_sizes, int n_in,
                              void* d_out, int out_size) {
    const float* x     = (const float*)d_in[0];
    const int*   ei    = (const int*)d_in[1];
    const float* W1    = (const float*)d_in[2];
    const float* b1    = (const float*)d_in[3];
    const float* W2    = (const float*)d_in[4];
    const float* b2    = (const float*)d_in[5];
    const float* Wg    = (const float*)d_in[6];
    const float* att_s = (const float*)d_in[7];
    const float* att_d = (const float*)d_in[8];
    const float* bg    = (const float*)d_in[9];
    const float* Wl1   = (const float*)d_in[10];
    const float* bl1   = (const float*)d_in[11];
    const float* Wl2   = (const float*)d_in[12];
    const float* bl2   = (const float*)d_in[13];
    const float* Wl3   = (const float*)d_in[14];
    const float* bl3   = (const float*)d_in[15];
    float* out = (float*)d_out;

    const int* src = ei;
    const int* dst = ei + Ee;

    float *A, *B, *H, *G, *M1, *M2;
    cudaGetSymbolAddress((void**)&A,  g_bufA);
    cudaGetSymbolAddress((void**)&B,  g_bufB);
    cudaGetSymbolAddress((void**)&H,  g_h);
    cudaGetSymbolAddress((void**)&G,  g_gat);
    cudaGetSymbolAddress((void**)&M1, g_m1);
    cudaGetSymbolAddress((void**)&M2, g_m2);

    // ---- preprocessing: degrees, dinv, CSR grouped by dst ----
    init_cnt<<<(Nn + 255) / 256, 256>>>();
    count_deg<<<(Ee + 255) / 256, 256>>>(dst);
    calc_dinv<<<(Nn + 255) / 256, 256>>>();
    scan_p1<<<NBLK, 256>>>();
    scan_p2<<<1, 128>>>();
    scan_p3<<<NBLK, 256>>>();
    fill_csr<<<(ET + 255) / 256, 256>>>(src, dst);

    const int WARP_GRID = (Nn * 32 + 255) / 256;   // 12500

    // ---- conv1: 2 hops + linear + lrelu(0.1) ----
    spmm128<<<WARP_GRID, 256>>>(x, A);
    spmm128<<<WARP_GRID, 256>>>(A, B);
    {
        dim3 g(1, (Nn + 127) / 128);
        gemm_t<128, 8><<<g, 256>>>(B, W1, b1, A, Nn, 128, 128, 0.1f, 1);
    }

    // ---- conv2: 2 hops + linear + lrelu(0.1) ----
    spmm128<<<WARP_GRID, 256>>>(A, B);
    spmm128<<<WARP_GRID, 256>>>(B, A);
    {
        dim3 g(1, (Nn + 127) / 128);
        gemm_t<128, 8><<<g, 256>>>(A, W2, b2, B, Nn, 128, 128, 0.1f, 1);
    }

    // ---- GAT ----
    {
        dim3 g(1, (Nn + 127) / 128);
        gemm_t<64, 4><<<g, 256>>>(B, Wg, (const float*)nullptr, H, Nn, 64, 128, 0.f, 0);
    }
    att_scores<<<WARP_GRID, 256>>>(H, att_s, att_d);
    gat_aggregate<<<WARP_GRID, 256>>>(H, bg, G);

    // ---- MLP head (G viewed as [10000, 640]) ----
    {
        dim3 g(512 / 128, (NG + 127) / 128);
        gemm_t<128, 8><<<g, 256>>>(G, Wl1, bl1, M1, NG, 512, 640, 0.1f, 1);
    }
    {
        dim3 g(256 / 128, (NG + 127) / 128);
        gemm_t<128, 8><<<g, 256>>>(M1, Wl2, bl2, M2, NG, 256, 512, 0.1f, 1);
    }
    final_layer<<<(NG + 31) / 32, 256>>>(M2, Wl3, bl3, out);
}

// round 6
// speedup vs baseline: 1.5372x; 1.3465x over previous
#include <cuda_runtime.h>
#include <cuda_bf16.h>
#include <mma.h>
#include <math.h>

using namespace nvcuda;

#define Nn 100000
#define Ee 1600000
#define ET (Ee + Nn)
#define NG 10000
#define NBLK 98   // ceil(Nn/1024)

// ---------------- scratch (static device memory; no allocs) ----------------
__device__ int   g_cnt[Nn];
__device__ int   g_rowptr[Nn + 1];
__device__ int   g_cursor[Nn];
__device__ int   g_col[ET];
__device__ float g_w[ET];
__device__ float g_dinv[Nn];
__device__ int   g_bsum[128];
__device__ int   g_boff[128];
__device__ float g_bufA[(size_t)Nn * 128];
__device__ float g_bufB[(size_t)Nn * 128];
__device__ float g_h[(size_t)Nn * 64];
__device__ float g_gat[(size_t)Nn * 64];
__device__ float g_as[Nn];
__device__ float g_ad[Nn];
__device__ float g_m1[(size_t)NG * 512];
__device__ float g_m2[(size_t)NG * 256];

// ---------------- preprocessing ----------------
__global__ void init_cnt() {
    int i = blockIdx.x * blockDim.x + threadIdx.x;
    if (i < Nn) g_cnt[i] = 1;
}

__global__ void count_deg(const int* __restrict__ dst) {
    int i = blockIdx.x * blockDim.x + threadIdx.x;
    if (i < Ee) atomicAdd(&g_cnt[dst[i]], 1);
}

__global__ void calc_dinv() {
    int i = blockIdx.x * blockDim.x + threadIdx.x;
    if (i < Nn) g_dinv[i] = rsqrtf((float)g_cnt[i]);
}

__global__ void __launch_bounds__(256) scan_p1() {
    __shared__ int ss[256];
    int b = blockIdx.x, t = threadIdx.x;
    int base = b * 1024 + t * 4;
    int4 v = make_int4(0, 0, 0, 0);
    if (base < Nn) v = *(const int4*)&g_cnt[base];
    ss[t] = v.x + v.y + v.z + v.w;
    __syncthreads();
    for (int off = 128; off > 0; off >>= 1) {
        if (t < off) ss[t] += ss[t + off];
        __syncthreads();
    }
    if (t == 0) g_bsum[b] = ss[0];
}

__global__ void scan_p2() {
    __shared__ int ss[128];
    int t = threadIdx.x;
    ss[t] = (t < NBLK) ? g_bsum[t] : 0;
    __syncthreads();
    for (int off = 1; off < 128; off <<= 1) {
        int u = (t >= off) ? ss[t - off] : 0;
        __syncthreads();
        ss[t] += u;
        __syncthreads();
    }
    g_boff[t] = (t == 0) ? 0 : ss[t - 1];
    if (t == 127) g_rowptr[Nn] = ss[127];
}

__global__ void __launch_bounds__(256) scan_p3() {
    __shared__ int ss[256];
    int b = blockIdx.x, t = threadIdx.x;
    int base = b * 1024 + t * 4;
    int4 v = make_int4(0, 0, 0, 0);
    if (base < Nn) v = *(const int4*)&g_cnt[base];
    int s0 = v.x, s1 = s0 + v.y, s2 = s1 + v.z, s3 = s2 + v.w;
    ss[t] = s3;
    __syncthreads();
    for (int off = 1; off < 256; off <<= 1) {
        int u = (t >= off) ? ss[t - off] : 0;
        __syncthreads();
        ss[t] += u;
        __syncthreads();
    }
    int ex = ((t == 0) ? 0 : ss[t - 1]) + g_boff[b];
    if (base < Nn) {
        int4 o = make_int4(ex, ex + s0, ex + s1, ex + s2);
        *(int4*)&g_rowptr[base] = o;
        *(int4*)&g_cursor[base] = o;
    }
}

__global__ void fill_csr(const int* __restrict__ src, const int* __restrict__ dst) {
    int i = blockIdx.x * blockDim.x + threadIdx.x;
    if (i >= ET) return;
    if (i < Ee) {
        int s = src[i], d = dst[i];
        int p = atomicAdd(&g_cursor[d], 1);
        g_col[p] = s;
        g_w[p] = g_dinv[s] * g_dinv[d];
    } else {
        int v = i - Ee;
        int p = atomicAdd(&g_cursor[v], 1);
        g_col[p] = v;
        float dv = g_dinv[v];
        g_w[p] = dv * dv;
    }
}

// ---------------- SpMM ----------------
__global__ void __launch_bounds__(256) spmm128(const float* __restrict__ in,
                                               float* __restrict__ out) {
    int w = (blockIdx.x * blockDim.x + threadIdx.x) >> 5;
    if (w >= Nn) return;
    int lane = threadIdx.x & 31;
    int beg = g_rowptr[w], end = g_rowptr[w + 1];
    const float4* in4 = (const float4*)in;
    float4 acc = make_float4(0.f, 0.f, 0.f, 0.f);
    for (int e = beg; e < end; ++e) {
        int s = g_col[e];
        float ww = g_w[e];
        float4 v = __ldg(&in4[(size_t)s * 32 + lane]);
        acc.x = fmaf(ww, v.x, acc.x);
        acc.y = fmaf(ww, v.y, acc.y);
        acc.z = fmaf(ww, v.z, acc.z);
        acc.w = fmaf(ww, v.w, acc.w);
    }
    ((float4*)out)[(size_t)w * 32 + lane] = acc;
}

// ================= WMMA bf16x3 GEMM =========================================
// C[M,Nc] = act(A[M,K] @ B[K,Nc] + bias). BM=128, BN=64, BK=16. K%16==0, Nc%64==0.
// fp32 emulated as Ahi*Bhi + Ahi*Blo + Alo*Bhi (bf16 hi/lo split).

__device__ __forceinline__ void split_bf(float x, __nv_bfloat16& h, __nv_bfloat16& l) {
    h = __float2bfloat16(x);
    l = __float2bfloat16(x - __bfloat162float(h));
}

#define ALD 24   // As leading dim (bf16 elems), mult of 8
#define BLD 72   // Bs leading dim
#define ELD 36   // epilogue buffer leading dim (floats), 36*4=144 mult of 16

__global__ void __launch_bounds__(256) gemm_wmma(
    const float* __restrict__ A, const float* __restrict__ Bm,
    const float* __restrict__ bias, float* __restrict__ C,
    int M, int Nc, int K, float slope, int act)
{
    extern __shared__ __align__(16) char sm[];
    __nv_bfloat16* As_hi = (__nv_bfloat16*)sm;            // [128][ALD]
    __nv_bfloat16* As_lo = As_hi + 128 * ALD;
    __nv_bfloat16* Bs_hi = As_lo + 128 * ALD;             // [16][BLD]
    __nv_bfloat16* Bs_lo = Bs_hi + 16 * BLD;
    float* ebuf = (float*)sm;                             // reused in epilogue

    int tid = threadIdx.x;
    int wid = tid >> 5, lane = tid & 31;
    int wr = wid >> 1, wc = wid & 1;                      // 4x2 warp grid
    int bm = blockIdx.y * 128, bn = blockIdx.x * 64;

    wmma::fragment<wmma::accumulator, 16, 16, 16, float> acc[2][2];
#pragma unroll
    for (int mi = 0; mi < 2; mi++)
#pragma unroll
        for (int ni = 0; ni < 2; ni++) wmma::fill_fragment(acc[mi][ni], 0.f);

    int aRow = tid >> 1;
    int aK = (tid & 1) * 8;
    bool aValid = (bm + aRow) < M;
    const float* Aptr = A + (size_t)(bm + aRow) * K + aK;
    int bRow = tid >> 4;
    int bCol = (tid & 15) * 4;
    const float* Bptr = Bm + (size_t)bRow * Nc + bn + bCol;

    for (int kc = 0; kc < K; kc += 16) {
        __syncthreads();
        // ---- A tile 128x16: split hi/lo ----
        {
            float4 v0 = make_float4(0.f, 0.f, 0.f, 0.f), v1 = v0;
            if (aValid) {
                v0 = __ldg((const float4*)(Aptr + kc));
                v1 = __ldg((const float4*)(Aptr + kc + 4));
            }
            __nv_bfloat16 h, l;
            __nv_bfloat16* ph = As_hi + aRow * ALD + aK;
            __nv_bfloat16* pl = As_lo + aRow * ALD + aK;
            split_bf(v0.x, h, l); ph[0] = h; pl[0] = l;
            split_bf(v0.y, h, l); ph[1] = h; pl[1] = l;
            split_bf(v0.z, h, l); ph[2] = h; pl[2] = l;
            split_bf(v0.w, h, l); ph[3] = h; pl[3] = l;
            split_bf(v1.x, h, l); ph[4] = h; pl[4] = l;
            split_bf(v1.y, h, l); ph[5] = h; pl[5] = l;
            split_bf(v1.z, h, l); ph[6] = h; pl[6] = l;
            split_bf(v1.w, h, l); ph[7] = h; pl[7] = l;
        }
        // ---- B tile 16x64: split hi/lo ----
        {
            float4 v = __ldg((const float4*)(Bptr + (size_t)kc * Nc));
            __nv_bfloat16 h, l;
            __nv_bfloat16* ph = Bs_hi + bRow * BLD + bCol;
            __nv_bfloat16* pl = Bs_lo + bRow * BLD + bCol;
            split_bf(v.x, h, l); ph[0] = h; pl[0] = l;
            split_bf(v.y, h, l); ph[1] = h; pl[1] = l;
            split_bf(v.z, h, l); ph[2] = h; pl[2] = l;
            split_bf(v.w, h, l); ph[3] = h; pl[3] = l;
        }
        __syncthreads();

        wmma::fragment<wmma::matrix_a, 16, 16, 16, __nv_bfloat16, wmma::row_major> ah[2], al[2];
#pragma unroll
        for (int mi = 0; mi < 2; mi++) {
            int r = wr * 32 + mi * 16;
            wmma::load_matrix_sync(ah[mi], As_hi + r * ALD, ALD);
            wmma::load_matrix_sync(al[mi], As_lo + r * ALD, ALD);
        }
#pragma unroll
        for (int ni = 0; ni < 2; ni++) {
            int c = wc * 32 + ni * 16;
            wmma::fragment<wmma::matrix_b, 16, 16, 16, __nv_bfloat16, wmma::row_major> bh, bl;
            wmma::load_matrix_sync(bh, Bs_hi + c, BLD);
            wmma::load_matrix_sync(bl, Bs_lo + c, BLD);
#pragma unroll
            for (int mi = 0; mi < 2; mi++) {
                wmma::mma_sync(acc[mi][ni], ah[mi], bh, acc[mi][ni]);
                wmma::mma_sync(acc[mi][ni], ah[mi], bl, acc[mi][ni]);
                wmma::mma_sync(acc[mi][ni], al[mi], bh, acc[mi][ni]);
            }
        }
    }

    // ---- epilogue: stage 32x32 per warp in smem, apply bias+act ----
    __syncthreads();
    float* wb = ebuf + wid * 32 * ELD;
#pragma unroll
    for (int mi = 0; mi < 2; mi++)
#pragma unroll
        for (int ni = 0; ni < 2; ni++)
            wmma::store_matrix_sync(wb + mi * 16 * ELD + ni * 16, acc[mi][ni],
                                    ELD, wmma::mem_row_major);

    int c = (lane & 7) * 4;
    int gc = bn + wc * 32 + c;
    float4 bv = make_float4(0.f, 0.f, 0.f, 0.f);
    if (bias) bv = *(const float4*)(bias + gc);
#pragma unroll
    for (int rr = 0; rr < 8; rr++) {
        int r = (lane >> 3) + rr * 4;          // rows 0..31, each exactly once
        int grow = bm + wr * 32 + r;
        if (grow < M) {
            float4 o = *(float4*)(wb + r * ELD + c);
            o.x += bv.x; o.y += bv.y; o.z += bv.z; o.w += bv.w;
            if (act) {
                o.x = o.x >= 0.f ? o.x : slope * o.x;
                o.y = o.y >= 0.f ? o.y : slope * o.y;
                o.z = o.z >= 0.f ? o.z : slope * o.z;
                o.w = o.w >= 0.f ? o.w : slope * o.w;
            }
            *(float4*)(C + (size_t)grow * Nc + gc) = o;
        }
    }
}

#define GEMM_SMEM (8 * 32 * ELD * 4 > (2 * 128 * ALD + 2 * 16 * BLD) * 2 ? \
                   8 * 32 * ELD * 4 : (2 * 128 * ALD + 2 * 16 * BLD) * 2)

// ---------------- GAT ----------------
__global__ void __launch_bounds__(256) att_scores(const float* __restrict__ h,
                                                  const float* __restrict__ att_s,
                                                  const float* __restrict__ att_d) {
    int w = (blockIdx.x * blockDim.x + threadIdx.x) >> 5;
    if (w >= Nn) return;
    int lane = threadIdx.x & 31;
    float h0 = h[(size_t)w * 64 + lane];
    float h1 = h[(size_t)w * 64 + 32 + lane];
    float s = h0 * att_s[lane] + h1 * att_s[32 + lane];
    float d = h0 * att_d[lane] + h1 * att_d[32 + lane];
#pragma unroll
    for (int off = 16; off > 0; off >>= 1) {
        s += __shfl_down_sync(0xffffffffu, s, off);
        d += __shfl_down_sync(0xffffffffu, d, off);
    }
    if (lane == 0) { g_as[w] = s; g_ad[w] = d; }
}

__global__ void __launch_bounds__(256) gat_aggregate(const float* __restrict__ h,
                                                     const float* __restrict__ bg,
                                                     float* __restrict__ out) {
    int row = (blockIdx.x * blockDim.x + threadIdx.x) >> 5;
    if (row >= Nn) return;
    int lane = threadIdx.x & 31;
    int beg = g_rowptr[row], end = g_rowptr[row + 1];
    float ad = g_ad[row];

    float m = -1e30f;
    for (int e = beg + lane; e < end; e += 32) {
        float v = g_as[g_col[e]] + ad;
        v = v >= 0.f ? v : 0.2f * v;
        m = fmaxf(m, v);
    }
#pragma unroll
    for (int off = 16; off > 0; off >>= 1)
        m = fmaxf(m, __shfl_xor_sync(0xffffffffu, m, off));

    const float2* h2 = (const float2*)h;
    float2 acc = make_float2(0.f, 0.f);
    float ssum = 0.f;
    for (int e = beg; e < end; ++e) {
        int s = g_col[e];
        float v = g_as[s] + ad;
        v = v >= 0.f ? v : 0.2f * v;
        float c = __expf(v - m);
        ssum += c;
        float2 hv = __ldg(&h2[(size_t)s * 32 + lane]);
        acc.x = fmaf(c, hv.x, acc.x);
        acc.y = fmaf(c, hv.y, acc.y);
    }
    float inv = 1.0f / ssum;
    float o0 = acc.x * inv + bg[2 * lane];
    float o1 = acc.y * inv + bg[2 * lane + 1];
    o0 = o0 >= 0.f ? o0 : 0.1f * o0;
    o1 = o1 >= 0.f ? o1 : 0.1f * o1;
    ((float2*)out)[(size_t)row * 32 + lane] = make_float2(o0, o1);
}

// ---------------- final 256 -> 8 layer ----------------
__global__ void __launch_bounds__(256) final_layer(const float* __restrict__ A,
                                                   const float* __restrict__ W,
                                                   const float* __restrict__ b,
                                                   float* __restrict__ out) {
    __shared__ float Ws[256 * 8];
    int t = threadIdx.x;
    for (int i = t; i < 256 * 8; i += 256) Ws[i] = W[i];
    __syncthreads();
    int g = blockIdx.x * 32 + (t >> 3);
    int c = t & 7;
    if (g >= NG) return;
    const float* a = A + (size_t)g * 256;
    float acc = 0.f;
#pragma unroll 4
    for (int k = 0; k < 256; k++) acc = fmaf(a[k], Ws[k * 8 + c], acc);
    out[(size_t)g * 8 + c] = acc + b[c];
}

// ---------------- host launcher ----------------
extern "C" void kernel_launch(void* const* d_in, const int* in_sizes, int n_in,
                              void* d_out, int out_size) {
    const float* x     = (const float*)d_in[0];
    const int*   ei    = (const int*)d_in[1];
    const float* W1    = (const float*)d_in[2];
    const float* b1    = (const float*)d_in[3];
    const float* W2    = (const float*)d_in[4];
    const float* b2    = (const float*)d_in[5];
    const float* Wg    = (const float*)d_in[6];
    const float* att_s = (const float*)d_in[7];
    const float* att_d = (const float*)d_in[8];
    const float* bg    = (const float*)d_in[9];
    const float* Wl1   = (const float*)d_in[10];
    const float* bl1   = (const float*)d_in[11];
    const float* Wl2   = (const float*)d_in[12];
    const float* bl2   = (const float*)d_in[13];
    const float* Wl3   = (const float*)d_in[14];
    const float* bl3   = (const float*)d_in[15];
    float* out = (float*)d_out;

    const int* src = ei;
    const int* dst = ei + Ee;

    float *A, *B, *H, *G, *M1, *M2;
    cudaGetSymbolAddress((void**)&A,  g_bufA);
    cudaGetSymbolAddress((void**)&B,  g_bufB);
    cudaGetSymbolAddress((void**)&H,  g_h);
    cudaGetSymbolAddress((void**)&G,  g_gat);
    cudaGetSymbolAddress((void**)&M1, g_m1);
    cudaGetSymbolAddress((void**)&M2, g_m2);

    // ---- preprocessing ----
    init_cnt<<<(Nn + 255) / 256, 256>>>();
    count_deg<<<(Ee + 255) / 256, 256>>>(dst);
    calc_dinv<<<(Nn + 255) / 256, 256>>>();
    scan_p1<<<NBLK, 256>>>();
    scan_p2<<<1, 128>>>();
    scan_p3<<<NBLK, 256>>>();
    fill_csr<<<(ET + 255) / 256, 256>>>(src, dst);

    const int WARP_GRID = (Nn * 32 + 255) / 256;
    const int MT_N = (Nn + 127) / 128;   // 782
    const int MT_G = (NG + 127) / 128;   // 79
    const int SMEM = GEMM_SMEM;

    // ---- conv1 ----
    spmm128<<<WARP_GRID, 256>>>(x, A);
    spmm128<<<WARP_GRID, 256>>>(A, B);
    gemm_wmma<<<dim3(2, MT_N), 256, SMEM>>>(B, W1, b1, A, Nn, 128, 128, 0.1f, 1);

    // ---- conv2 ----
    spmm128<<<WARP_GRID, 256>>>(A, B);
    spmm128<<<WARP_GRID, 256>>>(B, A);
    gemm_wmma<<<dim3(2, MT_N), 256, SMEM>>>(A, W2, b2, B, Nn, 128, 128, 0.1f, 1);

    // ---- GAT ----
    gemm_wmma<<<dim3(1, MT_N), 256, SMEM>>>(B, Wg, (const float*)nullptr, H, Nn, 64, 128, 0.f, 0);
    att_scores<<<WARP_GRID, 256>>>(H, att_s, att_d);
    gat_aggregate<<<WARP_GRID, 256>>>(H, bg, G);

    // ---- MLP head ----
    gemm_wmma<<<dim3(8, MT_G), 256, SMEM>>>(G, Wl1, bl1, M1, NG, 512, 640, 0.1f, 1);
    gemm_wmma<<<dim3(4, MT_G), 256, SMEM>>>(M1, Wl2, bl2, M2, NG, 256, 512, 0.1f, 1);
    final_layer<<<(NG + 31) / 32, 256>>>(M2, Wl3, bl3, out);
}

// round 7
// speedup vs baseline: 1.5920x; 1.0357x over previous
#include <cuda_runtime.h>
#include <cuda_bf16.h>
#include <cuda_fp16.h>
#include <mma.h>
#include <math.h>

using namespace nvcuda;

#define Nn 100000
#define Ee 1600000
#define ET (Ee + Nn)
#define NG 10000
#define NBLK 98   // ceil(Nn/1024)

// ---------------- scratch (static device memory; no allocs) ----------------
__device__ int   g_cnt[Nn];
__device__ int   g_rowptr[Nn + 1];
__device__ int   g_cursor[Nn];
__device__ int   g_col[ET];
__device__ float g_w[ET];
__device__ float g_dinv[Nn];
__device__ int   g_bsum[128];
__device__ int   g_boff[128];
__device__ float  g_bufA[(size_t)Nn * 128];
__device__ float  g_bufB[(size_t)Nn * 128];
__device__ __half g_h1[(size_t)Nn * 128];   // fp16 feature stream
__device__ __half g_h2[(size_t)Nn * 128];   // fp16 feature stream / GAT h
__device__ float g_gat[(size_t)Nn * 64];
__device__ float g_as[Nn];
__device__ float g_ad[Nn];
__device__ float g_m1[(size_t)NG * 512];
__device__ float g_m2[(size_t)NG * 256];

// ---------------- preprocessing ----------------
__global__ void init_cnt() {
    int i = blockIdx.x * blockDim.x + threadIdx.x;
    if (i < Nn) g_cnt[i] = 1;
}

__global__ void count_deg(const int* __restrict__ dst) {
    int i = blockIdx.x * blockDim.x + threadIdx.x;
    if (i < Ee) atomicAdd(&g_cnt[dst[i]], 1);
}

__global__ void calc_dinv() {
    int i = blockIdx.x * blockDim.x + threadIdx.x;
    if (i < Nn) g_dinv[i] = rsqrtf((float)g_cnt[i]);
}

__global__ void __launch_bounds__(256) scan_p1() {
    __shared__ int ss[256];
    int b = blockIdx.x, t = threadIdx.x;
    int base = b * 1024 + t * 4;
    int4 v = make_int4(0, 0, 0, 0);
    if (base < Nn) v = *(const int4*)&g_cnt[base];
    ss[t] = v.x + v.y + v.z + v.w;
    __syncthreads();
    for (int off = 128; off > 0; off >>= 1) {
        if (t < off) ss[t] += ss[t + off];
        __syncthreads();
    }
    if (t == 0) g_bsum[b] = ss[0];
}

__global__ void scan_p2() {
    __shared__ int ss[128];
    int t = threadIdx.x;
    ss[t] = (t < NBLK) ? g_bsum[t] : 0;
    __syncthreads();
    for (int off = 1; off < 128; off <<= 1) {
        int u = (t >= off) ? ss[t - off] : 0;
        __syncthreads();
        ss[t] += u;
        __syncthreads();
    }
    g_boff[t] = (t == 0) ? 0 : ss[t - 1];
    if (t == 127) g_rowptr[Nn] = ss[127];
}

__global__ void __launch_bounds__(256) scan_p3() {
    __shared__ int ss[256];
    int b = blockIdx.x, t = threadIdx.x;
    int base = b * 1024 + t * 4;
    int4 v = make_int4(0, 0, 0, 0);
    if (base < Nn) v = *(const int4*)&g_cnt[base];
    int s0 = v.x, s1 = s0 + v.y, s2 = s1 + v.z, s3 = s2 + v.w;
    ss[t] = s3;
    __syncthreads();
    for (int off = 1; off < 256; off <<= 1) {
        int u = (t >= off) ? ss[t - off] : 0;
        __syncthreads();
        ss[t] += u;
        __syncthreads();
    }
    int ex = ((t == 0) ? 0 : ss[t - 1]) + g_boff[b];
    if (base < Nn) {
        int4 o = make_int4(ex, ex + s0, ex + s1, ex + s2);
        *(int4*)&g_rowptr[base] = o;
        *(int4*)&g_cursor[base] = o;
    }
}

__global__ void fill_csr(const int* __restrict__ src, const int* __restrict__ dst) {
    int i = blockIdx.x * blockDim.x + threadIdx.x;
    if (i >= ET) return;
    if (i < Ee) {
        int s = src[i], d = dst[i];
        int p = atomicAdd(&g_cursor[d], 1);
        g_col[p] = s;
        g_w[p] = g_dinv[s] * g_dinv[d];
    } else {
        int v = i - Ee;
        int p = atomicAdd(&g_cursor[v], 1);
        g_col[p] = v;
        float dv = g_dinv[v];
        g_w[p] = dv * dv;
    }
}

// ---------------- fp32 -> fp16 convert ----------------
__global__ void __launch_bounds__(256) f2h(const float* __restrict__ in,
                                           __half* __restrict__ out, int n4) {
    int i = blockIdx.x * blockDim.x + threadIdx.x;
    if (i >= n4) return;
    float4 v = __ldg(&((const float4*)in)[i]);
    __half2 a = __floats2half2_rn(v.x, v.y);
    __half2 b = __floats2half2_rn(v.z, v.w);
    uint2 st;
    st.x = *(unsigned*)&a;
    st.y = *(unsigned*)&b;
    ((uint2*)out)[i] = st;
}

// ---------------- SpMM (fp16 gather, fp32 accumulate) ----------------
// out type: 0 = fp16, 1 = fp32
template<int OUT_F32>
__global__ void __launch_bounds__(256) spmm_h(const __half* __restrict__ in,
                                              void* __restrict__ out) {
    int w = (blockIdx.x * blockDim.x + threadIdx.x) >> 5;
    if (w >= Nn) return;
    int lane = threadIdx.x & 31;
    int beg = g_rowptr[w], end = g_rowptr[w + 1];
    const uint2* in2 = (const uint2*)in;   // row = 128 halves = 32 uint2
    float4 acc = make_float4(0.f, 0.f, 0.f, 0.f);
    for (int e = beg; e < end; ++e) {
        int s = g_col[e];
        float ww = g_w[e];
        uint2 v = __ldg(&in2[(size_t)s * 32 + lane]);
        float2 fa = __half22float2(*(__half2*)&v.x);
        float2 fb = __half22float2(*(__half2*)&v.y);
        acc.x = fmaf(ww, fa.x, acc.x);
        acc.y = fmaf(ww, fa.y, acc.y);
        acc.z = fmaf(ww, fb.x, acc.z);
        acc.w = fmaf(ww, fb.y, acc.w);
    }
    if (OUT_F32) {
        ((float4*)out)[(size_t)w * 32 + lane] = acc;
    } else {
        __half2 a = __floats2half2_rn(acc.x, acc.y);
        __half2 b = __floats2half2_rn(acc.z, acc.w);
        uint2 st;
        st.x = *(unsigned*)&a;
        st.y = *(unsigned*)&b;
        ((uint2*)out)[(size_t)w * 32 + lane] = st;
    }
}

// ================= WMMA bf16x3 GEMM =========================================
// C[M,Nc] = act(A[M,K] @ B[K,Nc] + bias). BM=128, BN=64 per block, BK=16.
// fp32 emulated as Ahi*Bhi + Ahi*Blo + Alo*Bhi. OutT = float or __half.

__device__ __forceinline__ void split_bf(float x, __nv_bfloat16& h, __nv_bfloat16& l) {
    h = __float2bfloat16(x);
    l = __float2bfloat16(x - __bfloat162float(h));
}

#define ALD 24
#define BLD 72
#define ELD 36

template<typename OutT>
__global__ void __launch_bounds__(256) gemm_wmma(
    const float* __restrict__ A, const float* __restrict__ Bm,
    const float* __restrict__ bias, OutT* __restrict__ C,
    int M, int Nc, int K, float slope, int act)
{
    extern __shared__ __align__(16) char sm[];
    __nv_bfloat16* As_hi = (__nv_bfloat16*)sm;
    __nv_bfloat16* As_lo = As_hi + 128 * ALD;
    __nv_bfloat16* Bs_hi = As_lo + 128 * ALD;
    __nv_bfloat16* Bs_lo = Bs_hi + 16 * BLD;
    float* ebuf = (float*)sm;

    int tid = threadIdx.x;
    int wid = tid >> 5, lane = tid & 31;
    int wr = wid >> 1, wc = wid & 1;
    int bm = blockIdx.y * 128, bn = blockIdx.x * 64;

    wmma::fragment<wmma::accumulator, 16, 16, 16, float> acc[2][2];
#pragma unroll
    for (int mi = 0; mi < 2; mi++)
#pragma unroll
        for (int ni = 0; ni < 2; ni++) wmma::fill_fragment(acc[mi][ni], 0.f);

    int aRow = tid >> 1;
    int aK = (tid & 1) * 8;
    bool aValid = (bm + aRow) < M;
    const float* Aptr = A + (size_t)(bm + aRow) * K + aK;
    int bRow = tid >> 4;
    int bCol = (tid & 15) * 4;
    const float* Bptr = Bm + (size_t)bRow * Nc + bn + bCol;

    for (int kc = 0; kc < K; kc += 16) {
        __syncthreads();
        {
            float4 v0 = make_float4(0.f, 0.f, 0.f, 0.f), v1 = v0;
            if (aValid) {
                v0 = __ldg((const float4*)(Aptr + kc));
                v1 = __ldg((const float4*)(Aptr + kc + 4));
            }
            __nv_bfloat16 h, l;
            __nv_bfloat16* ph = As_hi + aRow * ALD + aK;
            __nv_bfloat16* pl = As_lo + aRow * ALD + aK;
            split_bf(v0.x, h, l); ph[0] = h; pl[0] = l;
            split_bf(v0.y, h, l); ph[1] = h; pl[1] = l;
            split_bf(v0.z, h, l); ph[2] = h; pl[2] = l;
            split_bf(v0.w, h, l); ph[3] = h; pl[3] = l;
            split_bf(v1.x, h, l); ph[4] = h; pl[4] = l;
            split_bf(v1.y, h, l); ph[5] = h; pl[5] = l;
            split_bf(v1.z, h, l); ph[6] = h; pl[6] = l;
            split_bf(v1.w, h, l); ph[7] = h; pl[7] = l;
        }
        {
            float4 v = __ldg((const float4*)(Bptr + (size_t)kc * Nc));
            __nv_bfloat16 h, l;
            __nv_bfloat16* ph = Bs_hi + bRow * BLD + bCol;
            __nv_bfloat16* pl = Bs_lo + bRow * BLD + bCol;
            split_bf(v.x, h, l); ph[0] = h; pl[0] = l;
            split_bf(v.y, h, l); ph[1] = h; pl[1] = l;
            split_bf(v.z, h, l); ph[2] = h; pl[2] = l;
            split_bf(v.w, h, l); ph[3] = h; pl[3] = l;
        }
        __syncthreads();

        wmma::fragment<wmma::matrix_a, 16, 16, 16, __nv_bfloat16, wmma::row_major> ah[2], al[2];
#pragma unroll
        for (int mi = 0; mi < 2; mi++) {
            int r = wr * 32 + mi * 16;
            wmma::load_matrix_sync(ah[mi], As_hi + r * ALD, ALD);
            wmma::load_matrix_sync(al[mi], As_lo + r * ALD, ALD);
        }
#pragma unroll
        for (int ni = 0; ni < 2; ni++) {
            int c = wc * 32 + ni * 16;
            wmma::fragment<wmma::matrix_b, 16, 16, 16, __nv_bfloat16, wmma::row_major> bh, bl;
            wmma::load_matrix_sync(bh, Bs_hi + c, BLD);
            wmma::load_matrix_sync(bl, Bs_lo + c, BLD);
#pragma unroll
            for (int mi = 0; mi < 2; mi++) {
                wmma::mma_sync(acc[mi][ni], ah[mi], bh, acc[mi][ni]);
                wmma::mma_sync(acc[mi][ni], ah[mi], bl, acc[mi][ni]);
                wmma::mma_sync(acc[mi][ni], al[mi], bh, acc[mi][ni]);
            }
        }
    }

    __syncthreads();
    float* wb = ebuf + wid * 32 * ELD;
#pragma unroll
    for (int mi = 0; mi < 2; mi++)
#pragma unroll
        for (int ni = 0; ni < 2; ni++)
            wmma::store_matrix_sync(wb + mi * 16 * ELD + ni * 16, acc[mi][ni],
                                    ELD, wmma::mem_row_major);

    int c = (lane & 7) * 4;
    int gc = bn + wc * 32 + c;
    float4 bv = make_float4(0.f, 0.f, 0.f, 0.f);
    if (bias) bv = *(const float4*)(bias + gc);
#pragma unroll
    for (int rr = 0; rr < 8; rr++) {
        int r = (lane >> 3) + rr * 4;          // rows 0..31
        int grow = bm + wr * 32 + r;
        if (grow < M) {
            float4 o = *(float4*)(wb + r * ELD + c);
            o.x += bv.x; o.y += bv.y; o.z += bv.z; o.w += bv.w;
            if (act) {
                o.x = o.x >= 0.f ? o.x : slope * o.x;
                o.y = o.y >= 0.f ? o.y : slope * o.y;
                o.z = o.z >= 0.f ? o.z : slope * o.z;
                o.w = o.w >= 0.f ? o.w : slope * o.w;
            }
            if (sizeof(OutT) == 4) {
                *(float4*)((float*)C + (size_t)grow * Nc + gc) = o;
            } else {
                __half2 p0 = __floats2half2_rn(o.x, o.y);
                __half2 p1 = __floats2half2_rn(o.z, o.w);
                uint2 st;
                st.x = *(unsigned*)&p0;
                st.y = *(unsigned*)&p1;
                *(uint2*)((__half*)C + (size_t)grow * Nc + gc) = st;
            }
        }
    }
}

#define GEMM_SMEM (8 * 32 * ELD * 4 > (2 * 128 * ALD + 2 * 16 * BLD) * 2 ? \
                   8 * 32 * ELD * 4 : (2 * 128 * ALD + 2 * 16 * BLD) * 2)

// ---------------- GAT (fp16 h) ----------------
__global__ void __launch_bounds__(256) att_scores(const __half* __restrict__ h,
                                                  const float* __restrict__ att_s,
                                                  const float* __restrict__ att_d) {
    int w = (blockIdx.x * blockDim.x + threadIdx.x) >> 5;
    if (w >= Nn) return;
    int lane = threadIdx.x & 31;
    float h0 = __half2float(h[(size_t)w * 64 + lane]);
    float h1 = __half2float(h[(size_t)w * 64 + 32 + lane]);
    float s = h0 * att_s[lane] + h1 * att_s[32 + lane];
    float d = h0 * att_d[lane] + h1 * att_d[32 + lane];
#pragma unroll
    for (int off = 16; off > 0; off >>= 1) {
        s += __shfl_down_sync(0xffffffffu, s, off);
        d += __shfl_down_sync(0xffffffffu, d, off);
    }
    if (lane == 0) { g_as[w] = s; g_ad[w] = d; }
}

__global__ void __launch_bounds__(256) gat_aggregate(const __half* __restrict__ h,
                                                     const float* __restrict__ bg,
                                                     float* __restrict__ out) {
    int row = (blockIdx.x * blockDim.x + threadIdx.x) >> 5;
    if (row >= Nn) return;
    int lane = threadIdx.x & 31;
    int beg = g_rowptr[row], end = g_rowptr[row + 1];
    float ad = g_ad[row];

    float m = -1e30f;
    for (int e = beg + lane; e < end; e += 32) {
        float v = g_as[g_col[e]] + ad;
        v = v >= 0.f ? v : 0.2f * v;
        m = fmaxf(m, v);
    }
#pragma unroll
    for (int off = 16; off > 0; off >>= 1)
        m = fmaxf(m, __shfl_xor_sync(0xffffffffu, m, off));

    const __half2* h2 = (const __half2*)h;   // row = 64 halves = 32 half2
    float2 acc = make_float2(0.f, 0.f);
    float ssum = 0.f;
    for (int e = beg; e < end; ++e) {
        int s = g_col[e];
        float v = g_as[s] + ad;
        v = v >= 0.f ? v : 0.2f * v;
        float c = __expf(v - m);
        ssum += c;
        float2 hv = __half22float2(__ldg(&h2[(size_t)s * 32 + lane]));
        acc.x = fmaf(c, hv.x, acc.x);
        acc.y = fmaf(c, hv.y, acc.y);
    }
    float inv = 1.0f / ssum;
    float o0 = acc.x * inv + bg[2 * lane];
    float o1 = acc.y * inv + bg[2 * lane + 1];
    o0 = o0 >= 0.f ? o0 : 0.1f * o0;
    o1 = o1 >= 0.f ? o1 : 0.1f * o1;
    ((float2*)out)[(size_t)row * 32 + lane] = make_float2(o0, o1);
}

// ---------------- final 256 -> 8 layer ----------------
__global__ void __launch_bounds__(256) final_layer(const float* __restrict__ A,
                                                   const float* __restrict__ W,
                                                   const float* __restrict__ b,
                                                   float* __restrict__ out) {
    __shared__ float Ws[256 * 8];
    int t = threadIdx.x;
    for (int i = t; i < 256 * 8; i += 256) Ws[i] = W[i];
    __syncthreads();
    int g = blockIdx.x * 32 + (t >> 3);
    int c = t & 7;
    if (g >= NG) return;
    const float* a = A + (size_t)g * 256;
    float acc = 0.f;
#pragma unroll 4
    for (int k = 0; k < 256; k++) acc = fmaf(a[k], Ws[k * 8 + c], acc);
    out[(size_t)g * 8 + c] = acc + b[c];
}

// ---------------- host launcher ----------------
extern "C" void kernel_launch(void* const* d_in, const int* in_sizes, int n_in,
                              void* d_out, int out_size) {
    const float* x     = (const float*)d_in[0];
    const int*   ei    = (const int*)d_in[1];
    const float* W1    = (const float*)d_in[2];
    const float* b1    = (const float*)d_in[3];
    const float* W2    = (const float*)d_in[4];
    const float* b2    = (const float*)d_in[5];
    const float* Wg    = (const float*)d_in[6];
    const float* att_s = (const float*)d_in[7];
    const float* att_d = (const float*)d_in[8];
    const float* bg    = (const float*)d_in[9];
    const float* Wl1   = (const float*)d_in[10];
    const float* bl1   = (const float*)d_in[11];
    const float* Wl2   = (const float*)d_in[12];
    const float* bl2   = (const float*)d_in[13];
    const float* Wl3   = (const float*)d_in[14];
    const float* bl3   = (const float*)d_in[15];
    float* out = (float*)d_out;

    const int* src = ei;
    const int* dst = ei + Ee;

    float *A, *B, *G, *M1, *M2;
    __half *H1, *H2;
    cudaGetSymbolAddress((void**)&A,  g_bufA);
    cudaGetSymbolAddress((void**)&B,  g_bufB);
    cudaGetSymbolAddress((void**)&H1, g_h1);
    cudaGetSymbolAddress((void**)&H2, g_h2);
    cudaGetSymbolAddress((void**)&G,  g_gat);
    cudaGetSymbolAddress((void**)&M1, g_m1);
    cudaGetSymbolAddress((void**)&M2, g_m2);

    // ---- preprocessing ----
    init_cnt<<<(Nn + 255) / 256, 256>>>();
    count_deg<<<(Ee + 255) / 256, 256>>>(dst);
    calc_dinv<<<(Nn + 255) / 256, 256>>>();
    scan_p1<<<NBLK, 256>>>();
    scan_p2<<<1, 128>>>();
    scan_p3<<<NBLK, 256>>>();
    fill_csr<<<(ET + 255) / 256, 256>>>(src, dst);

    const int WARP_GRID = (Nn * 32 + 255) / 256;
    const int MT_N = (Nn + 127) / 128;
    const int MT_G = (NG + 127) / 128;
    const int SMEM = GEMM_SMEM;
    const int N4 = Nn * 128 / 4;

    // ---- conv1: x -> fp16, 2 hops, GEMM(W1) -> fp16 ----
    f2h<<<(N4 + 255) / 256, 256>>>(x, H1, N4);
    spmm_h<0><<<WARP_GRID, 256>>>(H1, H2);
    spmm_h<1><<<WARP_GRID, 256>>>(H2, A);
    gemm_wmma<__half><<<dim3(2, MT_N), 256, SMEM>>>(A, W1, b1, H1, Nn, 128, 128, 0.1f, 1);

    // ---- conv2: 2 hops, GEMM(W2) -> fp32 ----
    spmm_h<0><<<WARP_GRID, 256>>>(H1, H2);
    spmm_h<1><<<WARP_GRID, 256>>>(H2, A);
    gemm_wmma<float><<<dim3(2, MT_N), 256, SMEM>>>(A, W2, b2, B, Nn, 128, 128, 0.1f, 1);

    // ---- GAT: h = B @ Wg -> fp16 (reuse H2 as [Nn,64] fp16) ----
    gemm_wmma<__half><<<dim3(1, MT_N), 256, SMEM>>>(B, Wg, (const float*)nullptr, H2, Nn, 64, 128, 0.f, 0);
    att_scores<<<WARP_GRID, 256>>>(H2, att_s, att_d);
    gat_aggregate<<<WARP_GRID, 256>>>(H2, bg, G);

    // ---- MLP head ----
    gemm_wmma<float><<<dim3(8, MT_G), 256, SMEM>>>(G, Wl1, bl1, M1, NG, 512, 640, 0.1f, 1);
    gemm_wmma<float><<<dim3(4, MT_G), 256, SMEM>>>(M1, Wl2, bl2, M2, NG, 256, 512, 0.1f, 1);
    final_layer<<<(NG + 31) / 32, 256>>>(M2, Wl3, bl3, out);
}

// round 8
// speedup vs baseline: 1.6484x; 1.0354x over previous
#include <cuda_runtime.h>
#include <cuda_bf16.h>
#include <cuda_fp16.h>
#include <mma.h>
#include <math.h>

using namespace nvcuda;

#define Nn 100000
#define Ee 1600000
#define ET (Ee + Nn)
#define NG 10000
#define NBLK 98   // ceil(Nn/1024)

// ---------------- scratch (static device memory; no allocs) ----------------
__device__ int   g_cnt[Nn];
__device__ int   g_rowptr[Nn + 1];
__device__ int   g_cursor[Nn];
__device__ int   g_col[ET];
__device__ float g_w[ET];
__device__ float g_dinv[Nn];
__device__ int   g_bsum[128];
__device__ int   g_boff[128];
__device__ float  g_bufA[(size_t)Nn * 128];
__device__ float  g_bufB[(size_t)Nn * 128];
__device__ __half g_h1[(size_t)Nn * 128];
__device__ __half g_h2[(size_t)Nn * 128];
__device__ float g_gat[(size_t)Nn * 64];
__device__ float g_as[Nn];
__device__ float g_ad[Nn];
__device__ float g_m1[(size_t)NG * 512];
__device__ float g_m2[(size_t)NG * 256];

// ---------------- preprocessing ----------------
__global__ void init_cnt() {
    int i = blockIdx.x * blockDim.x + threadIdx.x;
    if (i < Nn) g_cnt[i] = 1;
}

__global__ void count_deg(const int* __restrict__ dst) {
    int i = blockIdx.x * blockDim.x + threadIdx.x;
    if (i < Ee) atomicAdd(&g_cnt[dst[i]], 1);
}

__global__ void calc_dinv() {
    int i = blockIdx.x * blockDim.x + threadIdx.x;
    if (i < Nn) g_dinv[i] = rsqrtf((float)g_cnt[i]);
}

__global__ void __launch_bounds__(256) scan_p1() {
    __shared__ int ss[256];
    int b = blockIdx.x, t = threadIdx.x;
    int base = b * 1024 + t * 4;
    int4 v = make_int4(0, 0, 0, 0);
    if (base < Nn) v = *(const int4*)&g_cnt[base];
    ss[t] = v.x + v.y + v.z + v.w;
    __syncthreads();
    for (int off = 128; off > 0; off >>= 1) {
        if (t < off) ss[t] += ss[t + off];
        __syncthreads();
    }
    if (t == 0) g_bsum[b] = ss[0];
}

__global__ void scan_p2() {
    __shared__ int ss[128];
    int t = threadIdx.x;
    ss[t] = (t < NBLK) ? g_bsum[t] : 0;
    __syncthreads();
    for (int off = 1; off < 128; off <<= 1) {
        int u = (t >= off) ? ss[t - off] : 0;
        __syncthreads();
        ss[t] += u;
        __syncthreads();
    }
    g_boff[t] = (t == 0) ? 0 : ss[t - 1];
    if (t == 127) g_rowptr[Nn] = ss[127];
}

__global__ void __launch_bounds__(256) scan_p3() {
    __shared__ int ss[256];
    int b = blockIdx.x, t = threadIdx.x;
    int base = b * 1024 + t * 4;
    int4 v = make_int4(0, 0, 0, 0);
    if (base < Nn) v = *(const int4*)&g_cnt[base];
    int s0 = v.x, s1 = s0 + v.y, s2 = s1 + v.z, s3 = s2 + v.w;
    ss[t] = s3;
    __syncthreads();
    for (int off = 1; off < 256; off <<= 1) {
        int u = (t >= off) ? ss[t - off] : 0;
        __syncthreads();
        ss[t] += u;
        __syncthreads();
    }
    int ex = ((t == 0) ? 0 : ss[t - 1]) + g_boff[b];
    if (base < Nn) {
        int4 o = make_int4(ex, ex + s0, ex + s1, ex + s2);
        *(int4*)&g_rowptr[base] = o;
        *(int4*)&g_cursor[base] = o;
    }
}

__global__ void fill_csr(const int* __restrict__ src, const int* __restrict__ dst) {
    int i = blockIdx.x * blockDim.x + threadIdx.x;
    if (i >= ET) return;
    if (i < Ee) {
        int s = src[i], d = dst[i];
        int p = atomicAdd(&g_cursor[d], 1);
        g_col[p] = s;
        g_w[p] = g_dinv[s] * g_dinv[d];
    } else {
        int v = i - Ee;
        int p = atomicAdd(&g_cursor[v], 1);
        g_col[p] = v;
        float dv = g_dinv[v];
        g_w[p] = dv * dv;
    }
}

// ---------------- fp32 -> fp16 convert ----------------
__global__ void __launch_bounds__(256) f2h(const float* __restrict__ in,
                                           __half* __restrict__ out, int n4) {
    int i = blockIdx.x * blockDim.x + threadIdx.x;
    if (i >= n4) return;
    float4 v = __ldg(&((const float4*)in)[i]);
    __half2 a = __floats2half2_rn(v.x, v.y);
    __half2 b = __floats2half2_rn(v.z, v.w);
    uint2 st;
    st.x = *(unsigned*)&a;
    st.y = *(unsigned*)&b;
    ((uint2*)out)[i] = st;
}

// ---------------- SpMM (fp16 gather, 2 edge-groups x unroll2 = MLP 4) ------
__device__ __forceinline__ void acc_u4(float* acc, uint4 v, float ww) {
    float2 f0 = __half22float2(*(__half2*)&v.x);
    float2 f1 = __half22float2(*(__half2*)&v.y);
    float2 f2 = __half22float2(*(__half2*)&v.z);
    float2 f3 = __half22float2(*(__half2*)&v.w);
    acc[0] = fmaf(ww, f0.x, acc[0]); acc[1] = fmaf(ww, f0.y, acc[1]);
    acc[2] = fmaf(ww, f1.x, acc[2]); acc[3] = fmaf(ww, f1.y, acc[3]);
    acc[4] = fmaf(ww, f2.x, acc[4]); acc[5] = fmaf(ww, f2.y, acc[5]);
    acc[6] = fmaf(ww, f3.x, acc[6]); acc[7] = fmaf(ww, f3.y, acc[7]);
}

template<int OUT_F32>
__global__ void __launch_bounds__(256) spmm_h(const __half* __restrict__ in,
                                              void* __restrict__ out) {
    int row = (blockIdx.x * blockDim.x + threadIdx.x) >> 5;
    if (row >= Nn) return;
    int lane = threadIdx.x & 31;
    int grp = lane >> 4;       // 0/1: edge group
    int gl = lane & 15;        // 16 lanes x uint4 = 128 halves
    int beg = g_rowptr[row], end = g_rowptr[row + 1];
    const uint4* in4 = (const uint4*)in;

    float acc[8];
#pragma unroll
    for (int j = 0; j < 8; j++) acc[j] = 0.f;

    int e = beg + grp;
    // two edges per group in flight (4 per warp)
    for (; e + 2 < end; e += 4) {
        int s0 = __ldg(&g_col[e]);
        int s1 = __ldg(&g_col[e + 2]);
        float w0 = __ldg(&g_w[e]);
        float w1 = __ldg(&g_w[e + 2]);
        uint4 v0 = __ldg(&in4[(size_t)s0 * 16 + gl]);
        uint4 v1 = __ldg(&in4[(size_t)s1 * 16 + gl]);
        acc_u4(acc, v0, w0);
        acc_u4(acc, v1, w1);
    }
    if (e < end) {
        int s0 = __ldg(&g_col[e]);
        float w0 = __ldg(&g_w[e]);
        uint4 v0 = __ldg(&in4[(size_t)s0 * 16 + gl]);
        acc_u4(acc, v0, w0);
    }
#pragma unroll
    for (int j = 0; j < 8; j++)
        acc[j] += __shfl_xor_sync(0xffffffffu, acc[j], 16);

    // feature base for this lane: gl*8; grp 0 writes elems 0-3, grp 1 elems 4-7
    if (OUT_F32) {
        float4 o = grp ? make_float4(acc[4], acc[5], acc[6], acc[7])
                       : make_float4(acc[0], acc[1], acc[2], acc[3]);
        *(float4*)((float*)out + (size_t)row * 128 + gl * 8 + grp * 4) = o;
    } else {
        __half2 p0, p1;
        if (grp) { p0 = __floats2half2_rn(acc[4], acc[5]); p1 = __floats2half2_rn(acc[6], acc[7]); }
        else     { p0 = __floats2half2_rn(acc[0], acc[1]); p1 = __floats2half2_rn(acc[2], acc[3]); }
        uint2 st;
        st.x = *(unsigned*)&p0;
        st.y = *(unsigned*)&p1;
        *(uint2*)((__half*)out + (size_t)row * 128 + gl * 8 + grp * 4) = st;
    }
}

// ================= WMMA bf16x3 GEMM =========================================
__device__ __forceinline__ void split_bf(float x, __nv_bfloat16& h, __nv_bfloat16& l) {
    h = __float2bfloat16(x);
    l = __float2bfloat16(x - __bfloat162float(h));
}

#define ALD 24
#define BLD 72
#define ELD 36

template<typename OutT>
__global__ void __launch_bounds__(256) gemm_wmma(
    const float* __restrict__ A, const float* __restrict__ Bm,
    const float* __restrict__ bias, OutT* __restrict__ C,
    int M, int Nc, int K, float slope, int act)
{
    extern __shared__ __align__(16) char sm[];
    __nv_bfloat16* As_hi = (__nv_bfloat16*)sm;
    __nv_bfloat16* As_lo = As_hi + 128 * ALD;
    __nv_bfloat16* Bs_hi = As_lo + 128 * ALD;
    __nv_bfloat16* Bs_lo = Bs_hi + 16 * BLD;
    float* ebuf = (float*)sm;

    int tid = threadIdx.x;
    int wid = tid >> 5, lane = tid & 31;
    int wr = wid >> 1, wc = wid & 1;
    int bm = blockIdx.y * 128, bn = blockIdx.x * 64;

    wmma::fragment<wmma::accumulator, 16, 16, 16, float> acc[2][2];
#pragma unroll
    for (int mi = 0; mi < 2; mi++)
#pragma unroll
        for (int ni = 0; ni < 2; ni++) wmma::fill_fragment(acc[mi][ni], 0.f);

    int aRow = tid >> 1;
    int aK = (tid & 1) * 8;
    bool aValid = (bm + aRow) < M;
    const float* Aptr = A + (size_t)(bm + aRow) * K + aK;
    int bRow = tid >> 4;
    int bCol = (tid & 15) * 4;
    const float* Bptr = Bm + (size_t)bRow * Nc + bn + bCol;

    for (int kc = 0; kc < K; kc += 16) {
        __syncthreads();
        {
            float4 v0 = make_float4(0.f, 0.f, 0.f, 0.f), v1 = v0;
            if (aValid) {
                v0 = __ldg((const float4*)(Aptr + kc));
                v1 = __ldg((const float4*)(Aptr + kc + 4));
            }
            __nv_bfloat16 h, l;
            __nv_bfloat16* ph = As_hi + aRow * ALD + aK;
            __nv_bfloat16* pl = As_lo + aRow * ALD + aK;
            split_bf(v0.x, h, l); ph[0] = h; pl[0] = l;
            split_bf(v0.y, h, l); ph[1] = h; pl[1] = l;
            split_bf(v0.z, h, l); ph[2] = h; pl[2] = l;
            split_bf(v0.w, h, l); ph[3] = h; pl[3] = l;
            split_bf(v1.x, h, l); ph[4] = h; pl[4] = l;
            split_bf(v1.y, h, l); ph[5] = h; pl[5] = l;
            split_bf(v1.z, h, l); ph[6] = h; pl[6] = l;
            split_bf(v1.w, h, l); ph[7] = h; pl[7] = l;
        }
        {
            float4 v = __ldg((const float4*)(Bptr + (size_t)kc * Nc));
            __nv_bfloat16 h, l;
            __nv_bfloat16* ph = Bs_hi + bRow * BLD + bCol;
            __nv_bfloat16* pl = Bs_lo + bRow * BLD + bCol;
            split_bf(v.x, h, l); ph[0] = h; pl[0] = l;
            split_bf(v.y, h, l); ph[1] = h; pl[1] = l;
            split_bf(v.z, h, l); ph[2] = h; pl[2] = l;
            split_bf(v.w, h, l); ph[3] = h; pl[3] = l;
        }
        __syncthreads();

        wmma::fragment<wmma::matrix_a, 16, 16, 16, __nv_bfloat16, wmma::row_major> ah[2], al[2];
#pragma unroll
        for (int mi = 0; mi < 2; mi++) {
            int r = wr * 32 + mi * 16;
            wmma::load_matrix_sync(ah[mi], As_hi + r * ALD, ALD);
            wmma::load_matrix_sync(al[mi], As_lo + r * ALD, ALD);
        }
#pragma unroll
        for (int ni = 0; ni < 2; ni++) {
            int c = wc * 32 + ni * 16;
            wmma::fragment<wmma::matrix_b, 16, 16, 16, __nv_bfloat16, wmma::row_major> bh, bl;
            wmma::load_matrix_sync(bh, Bs_hi + c, BLD);
            wmma::load_matrix_sync(bl, Bs_lo + c, BLD);
#pragma unroll
            for (int mi = 0; mi < 2; mi++) {
                wmma::mma_sync(acc[mi][ni], ah[mi], bh, acc[mi][ni]);
                wmma::mma_sync(acc[mi][ni], ah[mi], bl, acc[mi][ni]);
                wmma::mma_sync(acc[mi][ni], al[mi], bh, acc[mi][ni]);
            }
        }
    }

    __syncthreads();
    float* wb = ebuf + wid * 32 * ELD;
#pragma unroll
    for (int mi = 0; mi < 2; mi++)
#pragma unroll
        for (int ni = 0; ni < 2; ni++)
            wmma::store_matrix_sync(wb + mi * 16 * ELD + ni * 16, acc[mi][ni],
                                    ELD, wmma::mem_row_major);

    int c = (lane & 7) * 4;
    int gc = bn + wc * 32 + c;
    float4 bv = make_float4(0.f, 0.f, 0.f, 0.f);
    if (bias) bv = *(const float4*)(bias + gc);
#pragma unroll
    for (int rr = 0; rr < 8; rr++) {
        int r = (lane >> 3) + rr * 4;
        int grow = bm + wr * 32 + r;
        if (grow < M) {
            float4 o = *(float4*)(wb + r * ELD + c);
            o.x += bv.x; o.y += bv.y; o.z += bv.z; o.w += bv.w;
            if (act) {
                o.x = o.x >= 0.f ? o.x : slope * o.x;
                o.y = o.y >= 0.f ? o.y : slope * o.y;
                o.z = o.z >= 0.f ? o.z : slope * o.z;
                o.w = o.w >= 0.f ? o.w : slope * o.w;
            }
            if (sizeof(OutT) == 4) {
                *(float4*)((float*)C + (size_t)grow * Nc + gc) = o;
            } else {
                __half2 p0 = __floats2half2_rn(o.x, o.y);
                __half2 p1 = __floats2half2_rn(o.z, o.w);
                uint2 st;
                st.x = *(unsigned*)&p0;
                st.y = *(unsigned*)&p1;
                *(uint2*)((__half*)C + (size_t)grow * Nc + gc) = st;
            }
        }
    }
}

#define GEMM_SMEM (8 * 32 * ELD * 4 > (2 * 128 * ALD + 2 * 16 * BLD) * 2 ? \
                   8 * 32 * ELD * 4 : (2 * 128 * ALD + 2 * 16 * BLD) * 2)

// ---------------- GAT ----------------
__global__ void __launch_bounds__(256) att_scores(const __half* __restrict__ h,
                                                  const float* __restrict__ att_s,
                                                  const float* __restrict__ att_d) {
    int w = (blockIdx.x * blockDim.x + threadIdx.x) >> 5;
    if (w >= Nn) return;
    int lane = threadIdx.x & 31;
    float h0 = __half2float(h[(size_t)w * 64 + lane]);
    float h1 = __half2float(h[(size_t)w * 64 + 32 + lane]);
    float s = h0 * att_s[lane] + h1 * att_s[32 + lane];
    float d = h0 * att_d[lane] + h1 * att_d[32 + lane];
#pragma unroll
    for (int off = 16; off > 0; off >>= 1) {
        s += __shfl_down_sync(0xffffffffu, s, off);
        d += __shfl_down_sync(0xffffffffu, d, off);
    }
    if (lane == 0) { g_as[w] = s; g_ad[w] = d; }
}

// 4 edge-groups of 8 lanes, unroll2 => 8 gathers in flight per warp
__global__ void __launch_bounds__(256) gat_aggregate(const __half* __restrict__ h,
                                                     const float* __restrict__ bg,
                                                     float* __restrict__ out) {
    int row = (blockIdx.x * blockDim.x + threadIdx.x) >> 5;
    if (row >= Nn) return;
    int lane = threadIdx.x & 31;
    int grp = lane >> 3;      // 0..3
    int gl = lane & 7;        // 8 lanes x uint4 = 64 halves
    int beg = g_rowptr[row], end = g_rowptr[row + 1];
    float ad = g_ad[row];

    // pass 1: segment max (all 32 lanes strided)
    float m = -1e30f;
    for (int e = beg + lane; e < end; e += 32) {
        float v = g_as[__ldg(&g_col[e])] + ad;
        v = v >= 0.f ? v : 0.2f * v;
        m = fmaxf(m, v);
    }
#pragma unroll
    for (int off = 16; off > 0; off >>= 1)
        m = fmaxf(m, __shfl_xor_sync(0xffffffffu, m, off));

    // pass 2
    const uint4* h4 = (const uint4*)h;
    float acc[8];
#pragma unroll
    for (int j = 0; j < 8; j++) acc[j] = 0.f;
    float ssum = 0.f;

    int e = beg + grp;
    for (; e + 4 < end; e += 8) {
        int s0 = __ldg(&g_col[e]);
        int s1 = __ldg(&g_col[e + 4]);
        float v0 = g_as[s0] + ad;
        float v1 = g_as[s1] + ad;
        v0 = v0 >= 0.f ? v0 : 0.2f * v0;
        v1 = v1 >= 0.f ? v1 : 0.2f * v1;
        float c0 = __expf(v0 - m);
        float c1 = __expf(v1 - m);
        uint4 hv0 = __ldg(&h4[(size_t)s0 * 8 + gl]);
        uint4 hv1 = __ldg(&h4[(size_t)s1 * 8 + gl]);
        ssum += c0 + c1;
        acc_u4(acc, hv0, c0);
        acc_u4(acc, hv1, c1);
    }
    if (e < end) {
        int s0 = __ldg(&g_col[e]);
        float v0 = g_as[s0] + ad;
        v0 = v0 >= 0.f ? v0 : 0.2f * v0;
        float c0 = __expf(v0 - m);
        uint4 hv0 = __ldg(&h4[(size_t)s0 * 8 + gl]);
        ssum += c0;
        acc_u4(acc, hv0, c0);
    }
    // reduce across 4 groups (xor 8, 16)
#pragma unroll
    for (int off = 8; off <= 16; off <<= 1) {
        ssum += __shfl_xor_sync(0xffffffffu, ssum, off);
#pragma unroll
        for (int j = 0; j < 8; j++)
            acc[j] += __shfl_xor_sync(0xffffffffu, acc[j], off);
    }

    float inv = 1.0f / ssum;
    // lane (grp, gl) writes features gl*8 + grp*2 + {0,1}
    int f = gl * 8 + grp * 2;
    float o0 = acc[grp * 2]     * inv + __ldg(&bg[f]);
    float o1 = acc[grp * 2 + 1] * inv + __ldg(&bg[f + 1]);
    o0 = o0 >= 0.f ? o0 : 0.1f * o0;
    o1 = o1 >= 0.f ? o1 : 0.1f * o1;
    *(float2*)(out + (size_t)row * 64 + f) = make_float2(o0, o1);
}

// ---------------- final 256 -> 8 layer ----------------
__global__ void __launch_bounds__(256) final_layer(const float* __restrict__ A,
                                                   const float* __restrict__ W,
                                                   const float* __restrict__ b,
                                                   float* __restrict__ out) {
    __shared__ float Ws[256 * 8];
    int t = threadIdx.x;
    for (int i = t; i < 256 * 8; i += 256) Ws[i] = W[i];
    __syncthreads();
    int g = blockIdx.x * 32 + (t >> 3);
    int c = t & 7;
    if (g >= NG) return;
    const float* a = A + (size_t)g * 256;
    float acc = 0.f;
#pragma unroll 4
    for (int k = 0; k < 256; k++) acc = fmaf(a[k], Ws[k * 8 + c], acc);
    out[(size_t)g * 8 + c] = acc + b[c];
}

// ---------------- host launcher ----------------
extern "C" void kernel_launch(void* const* d_in, const int* in_sizes, int n_in,
                              void* d_out, int out_size) {
    const float* x     = (const float*)d_in[0];
    const int*   ei    = (const int*)d_in[1];
    const float* W1    = (const float*)d_in[2];
    const float* b1    = (const float*)d_in[3];
    const float* W2    = (const float*)d_in[4];
    const float* b2    = (const float*)d_in[5];
    const float* Wg    = (const float*)d_in[6];
    const float* att_s = (const float*)d_in[7];
    const float* att_d = (const float*)d_in[8];
    const float* bg    = (const float*)d_in[9];
    const float* Wl1   = (const float*)d_in[10];
    const float* bl1   = (const float*)d_in[11];
    const float* Wl2   = (const float*)d_in[12];
    const float* bl2   = (const float*)d_in[13];
    const float* Wl3   = (const float*)d_in[14];
    const float* bl3   = (const float*)d_in[15];
    float* out = (float*)d_out;

    const int* src = ei;
    const int* dst = ei + Ee;

    float *A, *B, *G, *M1, *M2;
    __half *H1, *H2;
    cudaGetSymbolAddress((void**)&A,  g_bufA);
    cudaGetSymbolAddress((void**)&B,  g_bufB);
    cudaGetSymbolAddress((void**)&H1, g_h1);
    cudaGetSymbolAddress((void**)&H2, g_h2);
    cudaGetSymbolAddress((void**)&G,  g_gat);
    cudaGetSymbolAddress((void**)&M1, g_m1);
    cudaGetSymbolAddress((void**)&M2, g_m2);

    // ---- preprocessing ----
    init_cnt<<<(Nn + 255) / 256, 256>>>();
    count_deg<<<(Ee + 255) / 256, 256>>>(dst);
    calc_dinv<<<(Nn + 255) / 256, 256>>>();
    scan_p1<<<NBLK, 256>>>();
    scan_p2<<<1, 128>>>();
    scan_p3<<<NBLK, 256>>>();
    fill_csr<<<(ET + 255) / 256, 256>>>(src, dst);

    const int WARP_GRID = (Nn * 32 + 255) / 256;
    const int MT_N = (Nn + 127) / 128;
    const int MT_G = (NG + 127) / 128;
    const int SMEM = GEMM_SMEM;
    const int N4 = Nn * 128 / 4;

    // ---- conv1 ----
    f2h<<<(N4 + 255) / 256, 256>>>(x, H1, N4);
    spmm_h<0><<<WARP_GRID, 256>>>(H1, H2);
    spmm_h<1><<<WARP_GRID, 256>>>(H2, A);
    gemm_wmma<__half><<<dim3(2, MT_N), 256, SMEM>>>(A, W1, b1, H1, Nn, 128, 128, 0.1f, 1);

    // ---- conv2 ----
    spmm_h<0><<<WARP_GRID, 256>>>(H1, H2);
    spmm_h<1><<<WARP_GRID, 256>>>(H2, A);
    gemm_wmma<float><<<dim3(2, MT_N), 256, SMEM>>>(A, W2, b2, B, Nn, 128, 128, 0.1f, 1);

    // ---- GAT ----
    gemm_wmma<__half><<<dim3(1, MT_N), 256, SMEM>>>(B, Wg, (const float*)nullptr, H2, Nn, 64, 128, 0.f, 0);
    att_scores<<<WARP_GRID, 256>>>(H2, att_s, att_d);
    gat_aggregate<<<WARP_GRID, 256>>>(H2, bg, G);

    // ---- MLP head ----
    gemm_wmma<float><<<dim3(8, MT_G), 256, SMEM>>>(G, Wl1, bl1, M1, NG, 512, 640, 0.1f, 1);
    gemm_wmma<float><<<dim3(4, MT_G), 256, SMEM>>>(M1, Wl2, bl2, M2, NG, 256, 512, 0.1f, 1);
    final_layer<<<(NG + 31) / 32, 256>>>(M2, Wl3, bl3, out);
}

// round 9
// speedup vs baseline: 1.6539x; 1.0034x over previous
#include <cuda_runtime.h>
#include <cuda_bf16.h>
#include <cuda_fp16.h>
#include <mma.h>
#include <math.h>

using namespace nvcuda;

#define Nn 100000
#define Ee 1600000
#define ET (Ee + Nn)
#define NG 10000
#define NBLK 98   // ceil(Nn/1024)

typedef __nv_bfloat16 bf16;

// ---------------- scratch ----------------
__device__ int   g_cnt[Nn];
__device__ int   g_rowptr[Nn + 1];
__device__ int   g_cursor[Nn];
__device__ int   g_col[ET];
__device__ float g_w[ET];
__device__ float g_dinv[Nn];
__device__ int   g_bsum[128];
__device__ int   g_boff[128];
__device__ float  g_bufA[(size_t)Nn * 128];   // aliased: PBhi/PBlo planes
__device__ float  g_bufB[(size_t)Nn * 128];   // aliased: Ghi/Glo planes
__device__ bf16   g_pah[(size_t)Nn * 128];    // A hi plane
__device__ bf16   g_pal[(size_t)Nn * 128];    // A lo plane
__device__ __half g_h1[(size_t)Nn * 128];
__device__ __half g_h2[(size_t)Nn * 128];
__device__ bf16  g_whi[640 * 512];
__device__ bf16  g_wlo[640 * 512];
__device__ float g_as[Nn];
__device__ float g_ad[Nn];
__device__ float g_m1[(size_t)NG * 512];      // aliased: M1hi/M1lo planes
__device__ float g_m2[(size_t)NG * 256];

// ---------------- preprocessing ----------------
__global__ void init_cnt() {
    int i = blockIdx.x * blockDim.x + threadIdx.x;
    if (i < Nn) g_cnt[i] = 1;
}

__global__ void count_deg(const int* __restrict__ dst) {
    int i = blockIdx.x * blockDim.x + threadIdx.x;
    if (i < Ee) atomicAdd(&g_cnt[dst[i]], 1);
}

__global__ void calc_dinv() {
    int i = blockIdx.x * blockDim.x + threadIdx.x;
    if (i < Nn) g_dinv[i] = rsqrtf((float)g_cnt[i]);
}

__global__ void __launch_bounds__(256) scan_p1() {
    __shared__ int ss[256];
    int b = blockIdx.x, t = threadIdx.x;
    int base = b * 1024 + t * 4;
    int4 v = make_int4(0, 0, 0, 0);
    if (base < Nn) v = *(const int4*)&g_cnt[base];
    ss[t] = v.x + v.y + v.z + v.w;
    __syncthreads();
    for (int off = 128; off > 0; off >>= 1) {
        if (t < off) ss[t] += ss[t + off];
        __syncthreads();
    }
    if (t == 0) g_bsum[b] = ss[0];
}

__global__ void scan_p2() {
    __shared__ int ss[128];
    int t = threadIdx.x;
    ss[t] = (t < NBLK) ? g_bsum[t] : 0;
    __syncthreads();
    for (int off = 1; off < 128; off <<= 1) {
        int u = (t >= off) ? ss[t - off] : 0;
        __syncthreads();
        ss[t] += u;
        __syncthreads();
    }
    g_boff[t] = (t == 0) ? 0 : ss[t - 1];
    if (t == 127) g_rowptr[Nn] = ss[127];
}

__global__ void __launch_bounds__(256) scan_p3() {
    __shared__ int ss[256];
    int b = blockIdx.x, t = threadIdx.x;
    int base = b * 1024 + t * 4;
    int4 v = make_int4(0, 0, 0, 0);
    if (base < Nn) v = *(const int4*)&g_cnt[base];
    int s0 = v.x, s1 = s0 + v.y, s2 = s1 + v.z, s3 = s2 + v.w;
    ss[t] = s3;
    __syncthreads();
    for (int off = 1; off < 256; off <<= 1) {
        int u = (t >= off) ? ss[t - off] : 0;
        __syncthreads();
        ss[t] += u;
        __syncthreads();
    }
    int ex = ((t == 0) ? 0 : ss[t - 1]) + g_boff[b];
    if (base < Nn) {
        int4 o = make_int4(ex, ex + s0, ex + s1, ex + s2);
        *(int4*)&g_rowptr[base] = o;
        *(int4*)&g_cursor[base] = o;
    }
}

__global__ void fill_csr(const int* __restrict__ src, const int* __restrict__ dst) {
    int i = blockIdx.x * blockDim.x + threadIdx.x;
    if (i >= ET) return;
    if (i < Ee) {
        int s = src[i], d = dst[i];
        int p = atomicAdd(&g_cursor[d], 1);
        g_col[p] = s;
        g_w[p] = g_dinv[s] * g_dinv[d];
    } else {
        int v = i - Ee;
        int p = atomicAdd(&g_cursor[v], 1);
        g_col[p] = v;
        float dv = g_dinv[v];
        g_w[p] = dv * dv;
    }
}

// ---------------- converts ----------------
__global__ void __launch_bounds__(256) f2h(const float* __restrict__ in,
                                           __half* __restrict__ out, int n4) {
    int i = blockIdx.x * blockDim.x + threadIdx.x;
    if (i >= n4) return;
    float4 v = __ldg(&((const float4*)in)[i]);
    __half2 a = __floats2half2_rn(v.x, v.y);
    __half2 b = __floats2half2_rn(v.z, v.w);
    uint2 st;
    st.x = *(unsigned*)&a;
    st.y = *(unsigned*)&b;
    ((uint2*)out)[i] = st;
}

__device__ __forceinline__ void split_bf(float x, bf16& h, bf16& l) {
    h = __float2bfloat16(x);
    l = __float2bfloat16(x - __bfloat162float(h));
}

__global__ void __launch_bounds__(256) wsplit(const float* __restrict__ w,
                                              bf16* __restrict__ hi,
                                              bf16* __restrict__ lo, int n4) {
    int i = blockIdx.x * blockDim.x + threadIdx.x;
    if (i >= n4) return;
    float4 v = __ldg(&((const float4*)w)[i]);
    bf16 h0, l0, h1, l1, h2, l2, h3, l3;
    split_bf(v.x, h0, l0); split_bf(v.y, h1, l1);
    split_bf(v.z, h2, l2); split_bf(v.w, h3, l3);
    __nv_bfloat162 a(h0, h1), b(h2, h3), c(l0, l1), d(l2, l3);
    uint2 sh, sl;
    sh.x = *(unsigned*)&a; sh.y = *(unsigned*)&b;
    sl.x = *(unsigned*)&c; sl.y = *(unsigned*)&d;
    ((uint2*)hi)[i] = sh;
    ((uint2*)lo)[i] = sl;
}

// ---------------- SpMM (fp16 gather, 2 groups x unroll2) ----------------
// OUT: 0 = fp16, 2 = split bf16 planes
__device__ __forceinline__ void acc_u4(float* acc, uint4 v, float ww) {
    float2 f0 = __half22float2(*(__half2*)&v.x);
    float2 f1 = __half22float2(*(__half2*)&v.y);
    float2 f2 = __half22float2(*(__half2*)&v.z);
    float2 f3 = __half22float2(*(__half2*)&v.w);
    acc[0] = fmaf(ww, f0.x, acc[0]); acc[1] = fmaf(ww, f0.y, acc[1]);
    acc[2] = fmaf(ww, f1.x, acc[2]); acc[3] = fmaf(ww, f1.y, acc[3]);
    acc[4] = fmaf(ww, f2.x, acc[4]); acc[5] = fmaf(ww, f2.y, acc[5]);
    acc[6] = fmaf(ww, f3.x, acc[6]); acc[7] = fmaf(ww, f3.y, acc[7]);
}

template<int OUT>
__global__ void __launch_bounds__(256) spmm_h(const __half* __restrict__ in,
                                              void* __restrict__ out,
                                              bf16* __restrict__ out_lo) {
    int row = (blockIdx.x * blockDim.x + threadIdx.x) >> 5;
    if (row >= Nn) return;
    int lane = threadIdx.x & 31;
    int grp = lane >> 4;
    int gl = lane & 15;
    int beg = g_rowptr[row], end = g_rowptr[row + 1];
    const uint4* in4 = (const uint4*)in;

    float acc[8];
#pragma unroll
    for (int j = 0; j < 8; j++) acc[j] = 0.f;

    int e = beg + grp;
    for (; e + 2 < end; e += 4) {
        int s0 = __ldg(&g_col[e]);
        int s1 = __ldg(&g_col[e + 2]);
        float w0 = __ldg(&g_w[e]);
        float w1 = __ldg(&g_w[e + 2]);
        uint4 v0 = __ldg(&in4[(size_t)s0 * 16 + gl]);
        uint4 v1 = __ldg(&in4[(size_t)s1 * 16 + gl]);
        acc_u4(acc, v0, w0);
        acc_u4(acc, v1, w1);
    }
    if (e < end) {
        int s0 = __ldg(&g_col[e]);
        float w0 = __ldg(&g_w[e]);
        uint4 v0 = __ldg(&in4[(size_t)s0 * 16 + gl]);
        acc_u4(acc, v0, w0);
    }
#pragma unroll
    for (int j = 0; j < 8; j++)
        acc[j] += __shfl_xor_sync(0xffffffffu, acc[j], 16);

    int fo = gl * 8 + grp * 4;
    if (OUT == 0) {
        __half2 p0, p1;
        if (grp) { p0 = __floats2half2_rn(acc[4], acc[5]); p1 = __floats2half2_rn(acc[6], acc[7]); }
        else     { p0 = __floats2half2_rn(acc[0], acc[1]); p1 = __floats2half2_rn(acc[2], acc[3]); }
        uint2 st;
        st.x = *(unsigned*)&p0;
        st.y = *(unsigned*)&p1;
        *(uint2*)((__half*)out + (size_t)row * 128 + fo) = st;
    } else {
        bf16 h0, l0, h1, l1, h2, l2, h3, l3;
        int b = grp * 4;
        split_bf(acc[b + 0], h0, l0); split_bf(acc[b + 1], h1, l1);
        split_bf(acc[b + 2], h2, l2); split_bf(acc[b + 3], h3, l3);
        __nv_bfloat162 ph0(h0, h1), ph1(h2, h3), pl0(l0, l1), pl1(l2, l3);
        uint2 sh, sl;
        sh.x = *(unsigned*)&ph0; sh.y = *(unsigned*)&ph1;
        sl.x = *(unsigned*)&pl0; sl.y = *(unsigned*)&pl1;
        *(uint2*)((bf16*)out + (size_t)row * 128 + fo) = sh;
        *(uint2*)(out_lo + (size_t)row * 128 + fo) = sl;
    }
}

// ================= WMMA bf16x3 GEMM, pre-split operands =====================
// C = act(A @ W + bias); A given as hi/lo bf16 planes [M,K], W as hi/lo [K,Nc].
// BM=128, BN=64/block, BK=16. OUTMODE: 0 fp32, 1 fp16, 2 split bf16 planes.
#define ALD 24
#define BLD 72
#define ELD 36

template<int OUTMODE>
__global__ void __launch_bounds__(256) gemm_bf(
    const bf16* __restrict__ Ahi, const bf16* __restrict__ Alo,
    const bf16* __restrict__ Whi, const bf16* __restrict__ Wlo,
    const float* __restrict__ bias, void* __restrict__ C0, bf16* __restrict__ C1,
    int M, int Nc, int K, float slope, int act)
{
    extern __shared__ __align__(16) char sm[];
    bf16* As_hi = (bf16*)sm;
    bf16* As_lo = As_hi + 128 * ALD;
    bf16* Bs_hi = As_lo + 128 * ALD;
    bf16* Bs_lo = Bs_hi + 16 * BLD;
    float* ebuf = (float*)sm;

    int tid = threadIdx.x;
    int wid = tid >> 5, lane = tid & 31;
    int wr = wid >> 1, wc = wid & 1;
    int bm = blockIdx.y * 128, bn = blockIdx.x * 64;

    wmma::fragment<wmma::accumulator, 16, 16, 16, float> acc[2][2];
#pragma unroll
    for (int mi = 0; mi < 2; mi++)
#pragma unroll
        for (int ni = 0; ni < 2; ni++) wmma::fill_fragment(acc[mi][ni], 0.f);

    int aRow = tid >> 1;
    int aK = (tid & 1) * 8;
    bool aValid = (bm + aRow) < M;
    size_t aBase = (size_t)(bm + aRow) * K + aK;
    // B: threads 0-127 stage hi plane, 128-255 stage lo plane
    int bt = tid & 127;
    int bRow = bt >> 3;
    int bCol = (bt & 7) * 8;
    const bf16* wsrc = (tid < 128 ? Whi : Wlo);
    bf16* bdst = (tid < 128 ? Bs_hi : Bs_lo) + bRow * BLD + bCol;

    for (int kc = 0; kc < K; kc += 16) {
        __syncthreads();
        {
            uint4 vh = make_uint4(0, 0, 0, 0), vl = vh;
            if (aValid) {
                vh = __ldg((const uint4*)(Ahi + aBase + kc));
                vl = __ldg((const uint4*)(Alo + aBase + kc));
            }
            *(uint4*)(As_hi + aRow * ALD + aK) = vh;
            *(uint4*)(As_lo + aRow * ALD + aK) = vl;
        }
        *(uint4*)bdst = __ldg((const uint4*)(wsrc + (size_t)(kc + bRow) * Nc + bn + bCol));
        __syncthreads();

        wmma::fragment<wmma::matrix_a, 16, 16, 16, bf16, wmma::row_major> ah[2], al[2];
#pragma unroll
        for (int mi = 0; mi < 2; mi++) {
            int r = wr * 32 + mi * 16;
            wmma::load_matrix_sync(ah[mi], As_hi + r * ALD, ALD);
            wmma::load_matrix_sync(al[mi], As_lo + r * ALD, ALD);
        }
#pragma unroll
        for (int ni = 0; ni < 2; ni++) {
            int c = wc * 32 + ni * 16;
            wmma::fragment<wmma::matrix_b, 16, 16, 16, bf16, wmma::row_major> bh, bl;
            wmma::load_matrix_sync(bh, Bs_hi + c, BLD);
            wmma::load_matrix_sync(bl, Bs_lo + c, BLD);
#pragma unroll
            for (int mi = 0; mi < 2; mi++) {
                wmma::mma_sync(acc[mi][ni], ah[mi], bh, acc[mi][ni]);
                wmma::mma_sync(acc[mi][ni], ah[mi], bl, acc[mi][ni]);
                wmma::mma_sync(acc[mi][ni], al[mi], bh, acc[mi][ni]);
            }
        }
    }

    __syncthreads();
    float* wb = ebuf + wid * 32 * ELD;
#pragma unroll
    for (int mi = 0; mi < 2; mi++)
#pragma unroll
        for (int ni = 0; ni < 2; ni++)
            wmma::store_matrix_sync(wb + mi * 16 * ELD + ni * 16, acc[mi][ni],
                                    ELD, wmma::mem_row_major);

    int c = (lane & 7) * 4;
    int gc = bn + wc * 32 + c;
    float4 bv = make_float4(0.f, 0.f, 0.f, 0.f);
    if (bias) bv = *(const float4*)(bias + gc);
#pragma unroll
    for (int rr = 0; rr < 8; rr++) {
        int r = (lane >> 3) + rr * 4;
        int grow = bm + wr * 32 + r;
        if (grow < M) {
            float4 o = *(float4*)(wb + r * ELD + c);
            o.x += bv.x; o.y += bv.y; o.z += bv.z; o.w += bv.w;
            if (act) {
                o.x = o.x >= 0.f ? o.x : slope * o.x;
                o.y = o.y >= 0.f ? o.y : slope * o.y;
                o.z = o.z >= 0.f ? o.z : slope * o.z;
                o.w = o.w >= 0.f ? o.w : slope * o.w;
            }
            size_t off = (size_t)grow * Nc + gc;
            if (OUTMODE == 0) {
                *(float4*)((float*)C0 + off) = o;
            } else if (OUTMODE == 1) {
                __half2 p0 = __floats2half2_rn(o.x, o.y);
                __half2 p1 = __floats2half2_rn(o.z, o.w);
                uint2 st;
                st.x = *(unsigned*)&p0;
                st.y = *(unsigned*)&p1;
                *(uint2*)((__half*)C0 + off) = st;
            } else {
                bf16 h0, l0, h1, l1, h2, l2, h3, l3;
                split_bf(o.x, h0, l0); split_bf(o.y, h1, l1);
                split_bf(o.z, h2, l2); split_bf(o.w, h3, l3);
                __nv_bfloat162 ph0(h0, h1), ph1(h2, h3), pl0(l0, l1), pl1(l2, l3);
                uint2 sh, sl;
                sh.x = *(unsigned*)&ph0; sh.y = *(unsigned*)&ph1;
                sl.x = *(unsigned*)&pl0; sl.y = *(unsigned*)&pl1;
                *(uint2*)((bf16*)C0 + off) = sh;
                *(uint2*)(C1 + off) = sl;
            }
        }
    }
}

#define GEMM_SMEM (8 * 32 * ELD * 4)

// ---------------- GAT ----------------
__global__ void __launch_bounds__(256) att_scores(const __half* __restrict__ h,
                                                  const float* __restrict__ att_s,
                                                  const float* __restrict__ att_d) {
    int w = (blockIdx.x * blockDim.x + threadIdx.x) >> 5;
    if (w >= Nn) return;
    int lane = threadIdx.x & 31;
    float h0 = __half2float(h[(size_t)w * 64 + lane]);
    float h1 = __half2float(h[(size_t)w * 64 + 32 + lane]);
    float s = h0 * att_s[lane] + h1 * att_s[32 + lane];
    float d = h0 * att_d[lane] + h1 * att_d[32 + lane];
#pragma unroll
    for (int off = 16; off > 0; off >>= 1) {
        s += __shfl_down_sync(0xffffffffu, s, off);
        d += __shfl_down_sync(0xffffffffu, d, off);
    }
    if (lane == 0) { g_as[w] = s; g_ad[w] = d; }
}

__global__ void __launch_bounds__(256) gat_aggregate(const __half* __restrict__ h,
                                                     const float* __restrict__ bg,
                                                     bf16* __restrict__ ohi,
                                                     bf16* __restrict__ olo) {
    int row = (blockIdx.x * blockDim.x + threadIdx.x) >> 5;
    if (row >= Nn) return;
    int lane = threadIdx.x & 31;
    int grp = lane >> 3;
    int gl = lane & 7;
    int beg = g_rowptr[row], end = g_rowptr[row + 1];
    float ad = g_ad[row];

    float m = -1e30f;
    for (int e = beg + lane; e < end; e += 32) {
        float v = g_as[__ldg(&g_col[e])] + ad;
        v = v >= 0.f ? v : 0.2f * v;
        m = fmaxf(m, v);
    }
#pragma unroll
    for (int off = 16; off > 0; off >>= 1)
        m = fmaxf(m, __shfl_xor_sync(0xffffffffu, m, off));

    const uint4* h4 = (const uint4*)h;
    float acc[8];
#pragma unroll
    for (int j = 0; j < 8; j++) acc[j] = 0.f;
    float ssum = 0.f;

    int e = beg + grp;
    for (; e + 4 < end; e += 8) {
        int s0 = __ldg(&g_col[e]);
        int s1 = __ldg(&g_col[e + 4]);
        float v0 = g_as[s0] + ad;
        float v1 = g_as[s1] + ad;
        v0 = v0 >= 0.f ? v0 : 0.2f * v0;
        v1 = v1 >= 0.f ? v1 : 0.2f * v1;
        float c0 = __expf(v0 - m);
        float c1 = __expf(v1 - m);
        uint4 hv0 = __ldg(&h4[(size_t)s0 * 8 + gl]);
        uint4 hv1 = __ldg(&h4[(size_t)s1 * 8 + gl]);
        ssum += c0 + c1;
        acc_u4(acc, hv0, c0);
        acc_u4(acc, hv1, c1);
    }
    if (e < end) {
        int s0 = __ldg(&g_col[e]);
        float v0 = g_as[s0] + ad;
        v0 = v0 >= 0.f ? v0 : 0.2f * v0;
        float c0 = __expf(v0 - m);
        uint4 hv0 = __ldg(&h4[(size_t)s0 * 8 + gl]);
        ssum += c0;
        acc_u4(acc, hv0, c0);
    }
#pragma unroll
    for (int off = 8; off <= 16; off <<= 1) {
        ssum += __shfl_xor_sync(0xffffffffu, ssum, off);
#pragma unroll
        for (int j = 0; j < 8; j++)
            acc[j] += __shfl_xor_sync(0xffffffffu, acc[j], off);
    }

    float inv = 1.0f / ssum;
    int f = gl * 8 + grp * 2;
    float o0 = acc[grp * 2]     * inv + __ldg(&bg[f]);
    float o1 = acc[grp * 2 + 1] * inv + __ldg(&bg[f + 1]);
    o0 = o0 >= 0.f ? o0 : 0.1f * o0;
    o1 = o1 >= 0.f ? o1 : 0.1f * o1;
    bf16 h0, l0, h1, l1;
    split_bf(o0, h0, l0);
    split_bf(o1, h1, l1);
    __nv_bfloat162 ph(h0, h1), pl(l0, l1);
    *(__nv_bfloat162*)(ohi + (size_t)row * 64 + f) = ph;
    *(__nv_bfloat162*)(olo + (size_t)row * 64 + f) = pl;
}

// ---------------- final 256 -> 8 layer ----------------
__global__ void __launch_bounds__(256) final_layer(const float* __restrict__ A,
                                                   const float* __restrict__ W,
                                                   const float* __restrict__ b,
                                                   float* __restrict__ out) {
    __shared__ float Ws[256 * 8];
    int t = threadIdx.x;
    for (int i = t; i < 256 * 8; i += 256) Ws[i] = W[i];
    __syncthreads();
    int g = blockIdx.x * 32 + (t >> 3);
    int c = t & 7;
    if (g >= NG) return;
    const float* a = A + (size_t)g * 256;
    float acc = 0.f;
#pragma unroll 4
    for (int k = 0; k < 256; k++) acc = fmaf(a[k], Ws[k * 8 + c], acc);
    out[(size_t)g * 8 + c] = acc + b[c];
}

// ---------------- host launcher ----------------
extern "C" void kernel_launch(void* const* d_in, const int* in_sizes, int n_in,
                              void* d_out, int out_size) {
    const float* x     = (const float*)d_in[0];
    const int*   ei    = (const int*)d_in[1];
    const float* W1    = (const float*)d_in[2];
    const float* b1    = (const float*)d_in[3];
    const float* W2    = (const float*)d_in[4];
    const float* b2    = (const float*)d_in[5];
    const float* Wg    = (const float*)d_in[6];
    const float* att_s = (const float*)d_in[7];
    const float* att_d = (const float*)d_in[8];
    const float* bg    = (const float*)d_in[9];
    const float* Wl1   = (const float*)d_in[10];
    const float* bl1   = (const float*)d_in[11];
    const float* Wl2   = (const float*)d_in[12];
    const float* bl2   = (const float*)d_in[13];
    const float* Wl3   = (const float*)d_in[14];
    const float* bl3   = (const float*)d_in[15];
    float* out = (float*)d_out;

    const int* src = ei;
    const int* dst = ei + Ee;

    float *fA, *fB, *fM1, *M2;
    bf16 *PAh, *PAl, *Whi, *Wlo;
    __half *H1, *H2;
    cudaGetSymbolAddress((void**)&fA,  g_bufA);
    cudaGetSymbolAddress((void**)&fB,  g_bufB);
    cudaGetSymbolAddress((void**)&PAh, g_pah);
    cudaGetSymbolAddress((void**)&PAl, g_pal);
    cudaGetSymbolAddress((void**)&H1,  g_h1);
    cudaGetSymbolAddress((void**)&H2,  g_h2);
    cudaGetSymbolAddress((void**)&Whi, g_whi);
    cudaGetSymbolAddress((void**)&Wlo, g_wlo);
    cudaGetSymbolAddress((void**)&fM1, g_m1);
    cudaGetSymbolAddress((void**)&M2,  g_m2);

    bf16* PBh = (bf16*)fA;               // conv2 out hi plane [Nn,128]
    bf16* PBl = PBh + (size_t)Nn * 128;
    bf16* Gh  = (bf16*)fB;               // GAT out hi plane [Nn,64]
    bf16* Gl  = Gh + (size_t)Nn * 64;
    bf16* M1h = (bf16*)fM1;              // MLP1 out hi plane [NG,512]
    bf16* M1l = M1h + (size_t)NG * 512;

    // ---- preprocessing ----
    f2h<<<(Nn * 128 / 4 + 255) / 256, 256>>>(x, H1, Nn * 128 / 4);
    init_cnt<<<(Nn + 255) / 256, 256>>>();
    count_deg<<<(Ee + 255) / 256, 256>>>(dst);
    calc_dinv<<<(Nn + 255) / 256, 256>>>();
    scan_p1<<<NBLK, 256>>>();
    scan_p2<<<1, 128>>>();
    scan_p3<<<NBLK, 256>>>();
    fill_csr<<<(ET + 255) / 256, 256>>>(src, dst);

    const int WARP_GRID = (Nn * 32 + 255) / 256;
    const int MT_N = (Nn + 127) / 128;
    const int MT_G = (NG + 127) / 128;
    const int SMEM = GEMM_SMEM;

    // ---- conv1 ----
    spmm_h<0><<<WARP_GRID, 256>>>(H1, H2, nullptr);
    spmm_h<2><<<WARP_GRID, 256>>>(H2, PAh, PAl);
    wsplit<<<(128 * 128 / 4 + 255) / 256, 256>>>(W1, Whi, Wlo, 128 * 128 / 4);
    gemm_bf<1><<<dim3(2, MT_N), 256, SMEM>>>(PAh, PAl, Whi, Wlo, b1, H1, nullptr,
                                             Nn, 128, 128, 0.1f, 1);

    // ---- conv2 ----
    spmm_h<0><<<WARP_GRID, 256>>>(H1, H2, nullptr);
    spmm_h<2><<<WARP_GRID, 256>>>(H2, PAh, PAl);
    wsplit<<<(128 * 128 / 4 + 255) / 256, 256>>>(W2, Whi, Wlo, 128 * 128 / 4);
    gemm_bf<2><<<dim3(2, MT_N), 256, SMEM>>>(PAh, PAl, Whi, Wlo, b2, PBh, PBl,
                                             Nn, 128, 128, 0.1f, 1);

    // ---- GAT ----
    wsplit<<<(128 * 64 / 4 + 255) / 256, 256>>>(Wg, Whi, Wlo, 128 * 64 / 4);
    gemm_bf<1><<<dim3(1, MT_N), 256, SMEM>>>(PBh, PBl, Whi, Wlo, (const float*)nullptr,
                                             H2, nullptr, Nn, 64, 128, 0.f, 0);
    att_scores<<<WARP_GRID, 256>>>(H2, att_s, att_d);
    gat_aggregate<<<WARP_GRID, 256>>>(H2, bg, Gh, Gl);

    // ---- MLP head ----
    wsplit<<<(640 * 512 / 4 + 255) / 256, 256>>>(Wl1, Whi, Wlo, 640 * 512 / 4);
    gemm_bf<2><<<dim3(8, MT_G), 256, SMEM>>>(Gh, Gl, Whi, Wlo, bl1, M1h, M1l,
                                             NG, 512, 640, 0.1f, 1);
    wsplit<<<(512 * 256 / 4 + 255) / 256, 256>>>(Wl2, Whi, Wlo, 512 * 256 / 4);
    gemm_bf<0><<<dim3(4, MT_G), 256, SMEM>>>(M1h, M1l, Whi, Wlo, bl2, M2, nullptr,
                                             NG, 256, 512, 0.1f, 1);
    final_layer<<<(NG + 31) / 32, 256>>>(M2, Wl3, bl3, out);
}